// round 13
// baseline (speedup 1.0000x reference)
#include <cuda_runtime.h>
#include <cuda_bf16.h>
#include <math.h>

typedef unsigned long long u64;
typedef unsigned int u32;
typedef unsigned short u16;
typedef __nv_bfloat16 bf16;
#define BMAX 131072

#define MMA16816(c, a, b0_, b1_)                                              \
    asm volatile("mma.sync.aligned.m16n8k16.row.col.f32.bf16.bf16.f32 "       \
                 "{%0,%1,%2,%3},{%4,%5,%6,%7},{%8,%9},{%0,%1,%2,%3};"         \
                 : "+f"((c)[0]), "+f"((c)[1]), "+f"((c)[2]), "+f"((c)[3])     \
                 : "r"((a)[0]), "r"((a)[1]), "r"((a)[2]), "r"((a)[3]),        \
                   "r"(b0_), "r"(b1_))

__device__ __forceinline__ void splitf(float x, u16& h, u16& l) {
    bf16 hb = __float2bfloat16_rn(x);
    bf16 lb = __float2bfloat16_rn(x - __bfloat162float(hb));
    h = *(u16*)&hb; l = *(u16*)&lb;
}

// ------------------------------ device globals ------------------------------
__device__ float g_q[256];
__device__ float g_wk[4 * 256];
__device__ float g_ck[4];
__device__ float g_tmp[256];
__device__ float g_Wof[256 * 512];
__device__ float g_bof[512];
__device__ float g_W5c[3 * 256 * 256];   // [b][k][n]
__device__ float g_b5c[3 * 256];
__device__ float g_e0[(size_t)BMAX * 256];
__device__ float g_e1[(size_t)BMAX * 256];
__device__ u16   g_Wmh[2 * 256 * 512], g_Wml[2 * 256 * 512];   // enc W [mod][n][k]
__device__ u16   g_Wvh[256 * 256],     g_Wvl[256 * 256];       // Wv^T  [n][k]
__device__ u16   g_W5h[3 * 256 * 256], g_W5l[3 * 256 * 256];   // W5c^T [b][n][k]
__device__ u16   g_Wch[80 * 256],      g_Wcl[80 * 256];        // Wc2^T [n][k]

// ---------------------------- setup kernel 1 --------------------------------
__global__ void setup_all(const float* __restrict__ fq, const float* __restrict__ Wq,
                          const float* __restrict__ bq, const float* __restrict__ Wk,
                          const float* __restrict__ bk, const float* __restrict__ bv,
                          const float* __restrict__ Wo, const float* __restrict__ bo,
                          const float* __restrict__ Wfp, const float* __restrict__ bfp) {
    __shared__ float sA[64 * 65];
    int t = threadIdx.x;
    if (blockIdx.x == 0) {
        {
            float s = bq[t];
#pragma unroll 8
            for (int k = 0; k < 256; k++) s = fmaf(fq[k], Wq[k * 256 + t], s);
            g_q[t] = s;
        }
        __syncthreads();
#pragma unroll
        for (int l = 0; l < 4; l++) {
            int idx = t + l * 256;
            int h = idx >> 8, j = idx & 255;
            float s = 0.f;
#pragma unroll 8
            for (int d = 0; d < 64; d++)
                s = fmaf(Wk[j * 256 + h * 64 + d], g_q[h * 64 + d], s);
            g_wk[h * 256 + j] = s;
        }
        if (t < 4) {
            float c = 0.f;
#pragma unroll 8
            for (int d = 0; d < 64; d++) c = fmaf(bk[t * 64 + d], g_q[t * 64 + d], c);
            g_ck[t] = c;
        }
        __syncthreads();
        {
            float s = bo[t];
#pragma unroll 8
            for (int k = 0; k < 256; k++) s = fmaf(bv[k], Wo[k * 256 + t], s);
            g_tmp[t] = s;
        }
        __syncthreads();
#pragma unroll
        for (int l = 0; l < 2; l++) {
            int j = t + l * 256;
            float s = bfp[j];
#pragma unroll 8
            for (int m = 0; m < 256; m++) s = fmaf(g_tmp[m], Wfp[m * 512 + j], s);
            g_bof[j] = s;
        }
        return;
    }
    int bid = blockIdx.x - 1;
    int tx = t & 31, ty = t >> 5;
    int it = bid >> 2, jt = bid & 3;
    float acc[8][4];
#pragma unroll
    for (int i = 0; i < 8; i++)
#pragma unroll
        for (int c = 0; c < 4; c++) acc[i][c] = 0.f;
    for (int mc = 0; mc < 256; mc += 64) {
        __syncthreads();
#pragma unroll
        for (int l = 0; l < 16; l++) {
            int idx = t + l * 256;
            int r = idx >> 6, k = idx & 63;
            sA[r * 65 + k] = Wo[(it * 64 + r) * 256 + mc + k];
        }
        __syncthreads();
#pragma unroll 2
        for (int k = 0; k < 64; k++) {
            const float* Wp = Wfp + (size_t)(mc + k) * 512 + jt * 128 + tx;
            float w[4];
#pragma unroll
            for (int c = 0; c < 4; c++) w[c] = Wp[c * 32];
#pragma unroll
            for (int i = 0; i < 8; i++) {
                float a = sA[(ty * 8 + i) * 65 + k];
#pragma unroll
                for (int c = 0; c < 4; c++) acc[i][c] = fmaf(a, w[c], acc[i][c]);
            }
        }
    }
    __syncthreads();
#pragma unroll
    for (int i = 0; i < 8; i++)
#pragma unroll
        for (int c = 0; c < 4; c++)
            g_Wof[(size_t)(it * 64 + ty * 8 + i) * 512 + jt * 128 + tx + 32 * c] =
                acc[i][c];
}

// ---------------------------- setup kernel 2 --------------------------------
__global__ void setup_fuse(const float* __restrict__ Wip, const float* __restrict__ Wtp,
                           const float* __restrict__ Wc1, const float* __restrict__ bip,
                           const float* __restrict__ btp, const float* __restrict__ bc1) {
    __shared__ float sA[64 * 65];
    int t = threadIdx.x;
    if (blockIdx.x == 24) {
#pragma unroll
        for (int b = 0; b < 3; b++) {
            const float* b5 = (b == 0) ? g_bof : (b == 1) ? bip : btp;
            float s = bc1[t];
#pragma unroll 8
            for (int m = 0; m < 512; m++) s = fmaf(b5[m], Wc1[m * 256 + t], s);
            g_b5c[b * 256 + t] = s;
        }
        return;
    }
    int b = blockIdx.x >> 3, bid = blockIdx.x & 7;
    int it = bid >> 1, jt = bid & 1;
    const float* A = (b == 0) ? g_Wof : (b == 1) ? Wip : Wtp;
    int tx = t & 31, ty = t >> 5;
    float acc[8][4];
#pragma unroll
    for (int i = 0; i < 8; i++)
#pragma unroll
        for (int c = 0; c < 4; c++) acc[i][c] = 0.f;
    for (int mc = 0; mc < 512; mc += 64) {
        __syncthreads();
#pragma unroll
        for (int l = 0; l < 16; l++) {
            int idx = t + l * 256;
            int r = idx >> 6, k = idx & 63;
            sA[r * 65 + k] = A[(size_t)(it * 64 + r) * 512 + mc + k];
        }
        __syncthreads();
#pragma unroll 2
        for (int m = 0; m < 64; m++) {
            const float* Wp = Wc1 + (size_t)(mc + m) * 256 + jt * 128 + tx;
            float w[4];
#pragma unroll
            for (int c = 0; c < 4; c++) w[c] = Wp[c * 32];
#pragma unroll
            for (int i = 0; i < 8; i++) {
                float a = sA[(ty * 8 + i) * 65 + m];
#pragma unroll
                for (int c = 0; c < 4; c++) acc[i][c] = fmaf(a, w[c], acc[i][c]);
            }
        }
    }
    __syncthreads();
#pragma unroll
    for (int i = 0; i < 8; i++)
#pragma unroll
        for (int c = 0; c < 4; c++)
            g_W5c[(size_t)b * 65536 + (size_t)(it * 64 + ty * 8 + i) * 256 +
                  jt * 128 + tx + 32 * c] = acc[i][c];
}

// ---------------- setup 3/4: split-convert weights ----------------
__global__ void setup_conv(const float* __restrict__ Wie, const float* __restrict__ Wte) {
    int idx = blockIdx.x * 256 + threadIdx.x;
    int mod = idx >> 17, loc = idx & 131071;
    int n = loc >> 9, k = loc & 511;
    const float* W = mod ? Wte : Wie;
    u16 h, l;
    splitf(W[(size_t)k * 256 + n], h, l);
    size_t o = (size_t)mod * 131072 + (size_t)n * 512 + k;
    g_Wmh[o] = h; g_Wml[o] = l;
}
__global__ void setup_conv2(const float* __restrict__ Wv, const float* __restrict__ Wc2) {
    int idx = blockIdx.x * 256 + threadIdx.x;
    u16 h, l;
    if (idx < 65536) {
        int n = idx >> 8, k = idx & 255;
        splitf(Wv[k * 256 + n], h, l);
        g_Wvh[n * 256 + k] = h; g_Wvl[n * 256 + k] = l;
    } else if (idx < 262144) {
        int t = idx - 65536, b = t >> 16, r = t & 65535;
        int n = r >> 8, k = r & 255;
        splitf(g_W5c[b * 65536 + k * 256 + n], h, l);
        g_W5h[b * 65536 + n * 256 + k] = h; g_W5l[b * 65536 + n * 256 + k] = l;
    } else if (idx < 282624) {
        int t = idx - 262144, n = t >> 8, k = t & 255;
        splitf(Wc2[k * 80 + n], h, l);
        g_Wch[n * 256 + k] = h; g_Wcl[n * 256 + k] = l;
    }
}

// ------------------- encoder kernel (HMMA, unchanged) -----------------------
#define ENC_STRIDE 264
#define ENC_SMEM (2 * 64 * ENC_STRIDE * 2)

__global__ void __launch_bounds__(256, 2)
enc_kernel(const float* __restrict__ img, const float* __restrict__ txt,
           const float* __restrict__ b_ie, const float* __restrict__ b_te) {
    extern __shared__ u16 smh[];
    u16* Ah = smh;
    u16* Al = smh + 64 * ENC_STRIDE;
    const int tid = threadIdx.x;
    const int lane = tid & 31, w = tid >> 5;
    const int g = lane >> 2, tig = lane & 3;
    const int mod = blockIdx.y;
    const size_t row0 = (size_t)blockIdx.x * 64;
    const float* X  = mod ? txt : img;
    const float* bb = mod ? b_te : b_ie;
    const u16* Wh = g_Wmh + (size_t)mod * 131072;
    const u16* Wl = g_Wml + (size_t)mod * 131072;
    float* eP = mod ? g_e1 : g_e0;
    float acc[2][8][4] = {};

    for (int kc = 0; kc < 512; kc += 256) {
        __syncthreads();
#pragma unroll
        for (int l = 0; l < 16; l++) {
            int idx = tid + l * 256;
            int r = idx >> 6, k4 = idx & 63;
            float4 v = *(const float4*)(X + (row0 + r) * 512 + kc + k4 * 4);
            u16 h[4], lo[4];
            splitf(v.x, h[0], lo[0]); splitf(v.y, h[1], lo[1]);
            splitf(v.z, h[2], lo[2]); splitf(v.w, h[3], lo[3]);
            u32 base = r * ENC_STRIDE + k4 * 4;
            *(u32*)(Ah + base)     = (u32)h[0] | ((u32)h[1] << 16);
            *(u32*)(Ah + base + 2) = (u32)h[2] | ((u32)h[3] << 16);
            *(u32*)(Al + base)     = (u32)lo[0] | ((u32)lo[1] << 16);
            *(u32*)(Al + base + 2) = (u32)lo[2] | ((u32)lo[3] << 16);
        }
        __syncthreads();
#pragma unroll 2
        for (int ks = 0; ks < 16; ks++) {
            int kof = kc + ks * 16;
            u32 ah[2][4], al[2][4];
#pragma unroll
            for (int mt = 0; mt < 2; mt++) {
                int m = w * 32 + mt * 16 + g;
                size_t o0 = (size_t)m * 512 + kof + 2 * tig, o8 = o0 + 8 * 512;
                ah[mt][0] = *(const u32*)(Wh + o0); ah[mt][1] = *(const u32*)(Wh + o8);
                ah[mt][2] = *(const u32*)(Wh + o0 + 8); ah[mt][3] = *(const u32*)(Wh + o8 + 8);
                al[mt][0] = *(const u32*)(Wl + o0); al[mt][1] = *(const u32*)(Wl + o8);
                al[mt][2] = *(const u32*)(Wl + o0 + 8); al[mt][3] = *(const u32*)(Wl + o8 + 8);
            }
            int ko = ks * 16;
#pragma unroll
            for (int nt = 0; nt < 8; nt++) {
                const u16* ar  = Ah + (nt * 8 + g) * ENC_STRIDE + ko;
                const u16* arl = Al + (nt * 8 + g) * ENC_STRIDE + ko;
                u32 bh0 = *(const u32*)(ar + 2 * tig);
                u32 bh1 = *(const u32*)(ar + 2 * tig + 8);
                u32 bl0 = *(const u32*)(arl + 2 * tig);
                u32 bl1 = *(const u32*)(arl + 2 * tig + 8);
#pragma unroll
                for (int mt = 0; mt < 2; mt++) {
                    MMA16816(acc[mt][nt], ah[mt], bh0, bh1);
                    MMA16816(acc[mt][nt], ah[mt], bl0, bl1);
                    MMA16816(acc[mt][nt], al[mt], bh0, bh1);
                }
            }
        }
    }
#pragma unroll
    for (int mt = 0; mt < 2; mt++) {
        int m0 = w * 32 + mt * 16 + g;
        float b0 = bb[m0], b8 = bb[m0 + 8];
#pragma unroll
        for (int nt = 0; nt < 8; nt++) {
            size_t r0 = row0 + nt * 8 + 2 * tig;
            float v;
            v = acc[mt][nt][0] + b0; eP[r0 * 256 + m0]           = v > 0.f ? v : 0.f;
            v = acc[mt][nt][1] + b0; eP[(r0 + 1) * 256 + m0]     = v > 0.f ? v : 0.f;
            v = acc[mt][nt][2] + b8; eP[r0 * 256 + m0 + 8]       = v > 0.f ? v : 0.f;
            v = acc[mt][nt][3] + b8; eP[(r0 + 1) * 256 + m0 + 8] = v > 0.f ? v : 0.f;
        }
    }
}

// --------------------------- tail kernel (HMMA) -----------------------------
// 32 rows/CTA (sorted), 256 threads, 2 CTAs/SM. Split-bf16 smem planes.
// GEMM1: q0=e0@Wv, q1=e1@Wv, epilogue lerp -> xs. GEMM2: branch W5c -> h1.
// GEMM3: Wc2 -> out.
#define SR 264
#define T_E0H 0
#define T_E0L 8448
#define T_E1H 16896
#define T_E1L 25344
#define T_XSH 33792
#define T_XSL 42240
#define T_FLT 50688
#define TAIL_SMEM 102400

__global__ void __launch_bounds__(256, 2)
tail_mma(const float* __restrict__ img, const float* __restrict__ txt,
         const float* __restrict__ bc1, const float* __restrict__ bc2,
         float* __restrict__ out) {
    extern __shared__ u16 sh[];
    u16* E0H = sh + T_E0H; u16* E0L = sh + T_E0L;
    u16* E1H = sh + T_E1H; u16* E1L = sh + T_E1L;
    u16* XSH = sh + T_XSH; u16* XSL = sh + T_XSL;
    float* sattn = (float*)(sh + T_FLT);
    int* sflag = (int*)(sattn + 128);
    int* sperm = sflag + 32;
    int* ssbr  = sperm + 32;
    int* snb   = ssbr + 32;
    float* scratch = (float*)(sh + T_XSH);  // overlays xs (dead until GEMM1 epi)

    const int tid = threadIdx.x, lane = tid & 31, w = tid >> 5;
    const int g = lane >> 2, tig = lane & 3;
    const size_t row0 = (size_t)blockIdx.x * 32;

    // P0: flags + sort
    for (int l = 0; l < 2; l++) {
        int task = tid + l * 256;
        int mod = task >> 8, r = (task >> 3) & 31, p = task & 7;
        const float* X = mod ? txt : img;
        const float4* xp = (const float4*)(X + (row0 + r) * 512 + p * 64);
        float s = 0.f;
#pragma unroll
        for (int u = 0; u < 16; u++) {
            float4 v = xp[u];
            s += v.x * v.x + v.y * v.y + v.z * v.z + v.w * v.w;
        }
        scratch[task] = s;
    }
    __syncthreads();
    if (tid < 32) {
        float si = 0.f, st = 0.f;
#pragma unroll
        for (int p = 0; p < 8; p++) { si += scratch[tid * 8 + p]; st += scratch[256 + tid * 8 + p]; }
        int fi = si > 1e-12f, ft = st > 1e-12f;
        sflag[tid] = (fi && ft) ? 1 : (fi ? 2 : (ft ? 3 : 0));
    }
    __syncthreads();
    if (tid == 0) {
        int cnt[4] = {0, 0, 0, 0};
        for (int r = 0; r < 32; r++) cnt[sflag[r]]++;
        int base[4];
        base[1] = 0; base[2] = cnt[1]; base[3] = cnt[1] + cnt[2]; base[0] = base[3] + cnt[3];
        for (int r = 0; r < 32; r++) {
            int f = sflag[r], s = base[f]++;
            sperm[s] = r; ssbr[s] = f;
        }
        *snb = cnt[1];
    }
    __syncthreads();

    // P1: stage e0/e1 split-bf16 (sorted) + per-head dot partials
    {
        int s = tid >> 3, p = tid & 7;
        size_t gr = row0 + sperm[s];
        int k0 = p * 32;
        float d[2][4] = {};
        for (int m2 = 0; m2 < 2; m2++) {
            const float* src = (m2 ? g_e1 : g_e0) + gr * 256 + k0;
            u16* PH = m2 ? E1H : E0H;
            u16* PL = m2 ? E1L : E0L;
#pragma unroll
            for (int q = 0; q < 8; q++) {
                float4 v = *(const float4*)(src + q * 4);
                float vv[4] = {v.x, v.y, v.z, v.w};
#pragma unroll
                for (int e = 0; e < 4; e++) {
                    int k = k0 + q * 4 + e;
                    u16 hh, ll;
                    splitf(vv[e], hh, ll);
                    PH[s * SR + k] = hh; PL[s * SR + k] = ll;
#pragma unroll
                    for (int h = 0; h < 4; h++) d[m2][h] = fmaf(vv[e], g_wk[h * 256 + k], d[m2][h]);
                }
            }
        }
#pragma unroll
        for (int h = 0; h < 4; h++) {
            scratch[(s * 8 + p) * 4 + h] = d[0][h];
            scratch[1024 + (s * 8 + p) * 4 + h] = d[1][h];
        }
    }
    __syncthreads();
    if (tid < 128) {
        int s = tid >> 2, h = tid & 3;
        float d0 = 0.f, d1 = 0.f;
#pragma unroll
        for (int p = 0; p < 8; p++) {
            d0 += scratch[(s * 8 + p) * 4 + h];
            d1 += scratch[1024 + (s * 8 + p) * 4 + h];
        }
        float s0 = (d0 + g_ck[h]) * 0.125f, s1 = (d1 + g_ck[h]) * 0.125f;
        float m = fmaxf(s0, s1);
        float e0 = expf(s0 - m), e1 = expf(s1 - m);
        sattn[s * 4 + h] = e0 / (e0 + e1);
    }
    __syncthreads();
    const int nb = *snb;

    // GEMM1: q0 = e0@Wv, q1 = e1@Wv (both-row tiles only); lerp epilogue -> xs
    {
        int h = w >> 1, cw = w * 32;
        if (nb > 0) {
            int ntmax = (nb + 7) >> 3;
            float q0a[2][4][4] = {}, q1a[2][4][4] = {};
            for (int ks = 0; ks < 16; ks++) {
                u32 ah[2][4], al[2][4];
#pragma unroll
                for (int mt = 0; mt < 2; mt++) {
                    int m = cw + mt * 16 + g;
                    size_t o = (size_t)m * 256 + ks * 16 + 2 * tig, o8 = o + 2048;
                    ah[mt][0] = *(const u32*)(g_Wvh + o); ah[mt][1] = *(const u32*)(g_Wvh + o8);
                    ah[mt][2] = *(const u32*)(g_Wvh + o + 8); ah[mt][3] = *(const u32*)(g_Wvh + o8 + 8);
                    al[mt][0] = *(const u32*)(g_Wvl + o); al[mt][1] = *(const u32*)(g_Wvl + o8);
                    al[mt][2] = *(const u32*)(g_Wvl + o + 8); al[mt][3] = *(const u32*)(g_Wvl + o8 + 8);
                }
                for (int nt = 0; nt < ntmax; nt++) {
                    int base = (nt * 8 + g) * SR + ks * 16 + 2 * tig;
                    u32 x0h0 = *(const u32*)(E0H + base), x0h1 = *(const u32*)(E0H + base + 8);
                    u32 x0l0 = *(const u32*)(E0L + base), x0l1 = *(const u32*)(E0L + base + 8);
                    u32 x1h0 = *(const u32*)(E1H + base), x1h1 = *(const u32*)(E1H + base + 8);
                    u32 x1l0 = *(const u32*)(E1L + base), x1l1 = *(const u32*)(E1L + base + 8);
#pragma unroll
                    for (int mt = 0; mt < 2; mt++) {
                        MMA16816(q0a[mt][nt], ah[mt], x0h0, x0h1);
                        MMA16816(q0a[mt][nt], ah[mt], x0l0, x0l1);
                        MMA16816(q0a[mt][nt], al[mt], x0h0, x0h1);
                        MMA16816(q1a[mt][nt], ah[mt], x1h0, x1h1);
                        MMA16816(q1a[mt][nt], ah[mt], x1l0, x1l1);
                        MMA16816(q1a[mt][nt], al[mt], x1h0, x1h1);
                    }
                }
            }
            for (int nt = 0; nt < ntmax; nt++)
#pragma unroll
                for (int mt = 0; mt < 2; mt++) {
                    int r0 = nt * 8 + 2 * tig, m0 = cw + mt * 16 + g;
#pragma unroll
                    for (int pr = 0; pr < 2; pr++) {
                        int r = r0 + pr;
                        if (r >= nb) continue;
                        float a0 = sattn[r * 4 + h];
                        float v0 = fmaf(a0, q0a[mt][nt][pr] - q1a[mt][nt][pr],
                                        q1a[mt][nt][pr]);
                        float v8 = fmaf(a0, q0a[mt][nt][2 + pr] - q1a[mt][nt][2 + pr],
                                        q1a[mt][nt][2 + pr]);
                        u16 hh, ll;
                        splitf(v0, hh, ll); XSH[r * SR + m0] = hh;     XSL[r * SR + m0] = ll;
                        splitf(v8, hh, ll); XSH[r * SR + m0 + 8] = hh; XSL[r * SR + m0 + 8] = ll;
                    }
                }
        }
    }
    __syncthreads();

    // P4: xs for non-both rows (copy e0/e1 or zero)
    for (int idx = tid; idx < 32 * 8; idx += 256) {
        int s = idx >> 3, q = idx & 7;
        if (s < nb) continue;
        int f = ssbr[s];
        uint4 z = make_uint4(0, 0, 0, 0);
#pragma unroll
        for (int j = 0; j < 4; j++) {
            uint4 vh = z, vl = z;
            if (f == 2) {
                vh = ((const uint4*)(E0H + s * SR))[q * 4 + j];
                vl = ((const uint4*)(E0L + s * SR))[q * 4 + j];
            } else if (f == 3) {
                vh = ((const uint4*)(E1H + s * SR))[q * 4 + j];
                vl = ((const uint4*)(E1L + s * SR))[q * 4 + j];
            }
            ((uint4*)(XSH + s * SR))[q * 4 + j] = vh;
            ((uint4*)(XSL + s * SR))[q * 4 + j] = vl;
        }
    }
    __syncthreads();

    // GEMM2: h1 = relu(xs @ W5c[branch] + bias) -> overlay e0 planes
    {
        int cw = w * 32;
        float a2[2][4][4] = {};
        for (int seg = 1; seg <= 3; seg++) {
            u32 ntm = 0;
            for (int i = 0; i < 32; i++)
                if (ssbr[i] == seg) ntm |= 1u << (i >> 3);
            if (!ntm) continue;
            const u16* WH = g_W5h + (size_t)(seg - 1) * 65536;
            const u16* WL = g_W5l + (size_t)(seg - 1) * 65536;
            for (int ks = 0; ks < 16; ks++) {
                u32 ah[2][4], al[2][4];
#pragma unroll
                for (int mt = 0; mt < 2; mt++) {
                    int m = cw + mt * 16 + g;
                    size_t o = (size_t)m * 256 + ks * 16 + 2 * tig, o8 = o + 2048;
                    ah[mt][0] = *(const u32*)(WH + o); ah[mt][1] = *(const u32*)(WH + o8);
                    ah[mt][2] = *(const u32*)(WH + o + 8); ah[mt][3] = *(const u32*)(WH + o8 + 8);
                    al[mt][0] = *(const u32*)(WL + o); al[mt][1] = *(const u32*)(WL + o8);
                    al[mt][2] = *(const u32*)(WL + o + 8); al[mt][3] = *(const u32*)(WL + o8 + 8);
                }
                for (int nt = 0; nt < 4; nt++) {
                    if (!((ntm >> nt) & 1)) continue;
                    int s = nt * 8 + g;
                    bool on = (ssbr[s] == seg);
                    int base = s * SR + ks * 16 + 2 * tig;
                    u32 bh0 = 0, bh1 = 0, bl0 = 0, bl1 = 0;
                    if (on) {
                        bh0 = *(const u32*)(XSH + base); bh1 = *(const u32*)(XSH + base + 8);
                        bl0 = *(const u32*)(XSL + base); bl1 = *(const u32*)(XSL + base + 8);
                    }
#pragma unroll
                    for (int mt = 0; mt < 2; mt++) {
                        MMA16816(a2[mt][nt], ah[mt], bh0, bh1);
                        MMA16816(a2[mt][nt], ah[mt], bl0, bl1);
                        MMA16816(a2[mt][nt], al[mt], bh0, bh1);
                    }
                }
            }
        }
        for (int nt = 0; nt < 4; nt++)
#pragma unroll
            for (int mt = 0; mt < 2; mt++) {
                int r0 = nt * 8 + 2 * tig, m0 = cw + mt * 16 + g;
#pragma unroll
                for (int pr = 0; pr < 2; pr++) {
                    int r = r0 + pr;
                    int f = ssbr[r];
                    float b0 = f ? g_b5c[(f - 1) * 256 + m0] : bc1[m0];
                    float b8 = f ? g_b5c[(f - 1) * 256 + m0 + 8] : bc1[m0 + 8];
                    float v0 = a2[mt][nt][pr] + b0;     v0 = v0 > 0.f ? v0 : 0.f;
                    float v8 = a2[mt][nt][2 + pr] + b8; v8 = v8 > 0.f ? v8 : 0.f;
                    u16 hh, ll;
                    splitf(v0, hh, ll); E0H[r * SR + m0] = hh;     E0L[r * SR + m0] = ll;
                    splitf(v8, hh, ll); E0H[r * SR + m0 + 8] = hh; E0L[r * SR + m0 + 8] = ll;
                }
            }
    }
    __syncthreads();

    // GEMM3: out = h1 @ Wc2 + bc2 (warps 0..4, 16 cols each)
    if (w < 5) {
        float a3[4][4] = {};
        for (int ks = 0; ks < 16; ks++) {
            int m = w * 16 + g;
            size_t o = (size_t)m * 256 + ks * 16 + 2 * tig, o8 = o + 2048;
            u32 ah[4] = {*(const u32*)(g_Wch + o), *(const u32*)(g_Wch + o8),
                         *(const u32*)(g_Wch + o + 8), *(const u32*)(g_Wch + o8 + 8)};
            u32 al[4] = {*(const u32*)(g_Wcl + o), *(const u32*)(g_Wcl + o8),
                         *(const u32*)(g_Wcl + o + 8), *(const u32*)(g_Wcl + o8 + 8)};
#pragma unroll
            for (int nt = 0; nt < 4; nt++) {
                int base = (nt * 8 + g) * SR + ks * 16 + 2 * tig;
                u32 bh0 = *(const u32*)(E0H + base), bh1 = *(const u32*)(E0H + base + 8);
                u32 bl0 = *(const u32*)(E0L + base), bl1 = *(const u32*)(E0L + base + 8);
                MMA16816(a3[nt], ah, bh0, bh1);
                MMA16816(a3[nt], ah, bl0, bl1);
                MMA16816(a3[nt], al, bh0, bh1);
            }
        }
#pragma unroll
        for (int nt = 0; nt < 4; nt++) {
            int r0 = nt * 8 + 2 * tig, m0 = w * 16 + g;
#pragma unroll
            for (int pr = 0; pr < 2; pr++) {
                size_t ro = (row0 + sperm[r0 + pr]) * 80;
                out[ro + m0]     = a3[nt][pr] + bc2[m0];
                out[ro + m0 + 8] = a3[nt][2 + pr] + bc2[m0 + 8];
            }
        }
    }
}

// ------------------------------- launch ------------------------------------
extern "C" void kernel_launch(void* const* d_in, const int* in_sizes, int n_in,
                              void* d_out, int out_size) {
    const float* img  = (const float*)d_in[0];
    const float* txt  = (const float*)d_in[1];
    const float* W_ie = (const float*)d_in[2];
    const float* b_ie = (const float*)d_in[3];
    const float* W_te = (const float*)d_in[4];
    const float* b_te = (const float*)d_in[5];
    const float* fq   = (const float*)d_in[6];
    const float* Wq   = (const float*)d_in[7];
    const float* bq   = (const float*)d_in[8];
    const float* Wk   = (const float*)d_in[9];
    const float* bk   = (const float*)d_in[10];
    const float* Wv   = (const float*)d_in[11];
    const float* bv   = (const float*)d_in[12];
    const float* Wo   = (const float*)d_in[13];
    const float* bo   = (const float*)d_in[14];
    const float* W_ip = (const float*)d_in[15];
    const float* b_ip = (const float*)d_in[16];
    const float* W_tp = (const float*)d_in[17];
    const float* b_tp = (const float*)d_in[18];
    const float* W_fp = (const float*)d_in[19];
    const float* b_fp = (const float*)d_in[20];
    const float* Wc1  = (const float*)d_in[21];
    const float* bc1  = (const float*)d_in[22];
    const float* Wc2  = (const float*)d_in[23];
    const float* bc2  = (const float*)d_in[24];
    float* out = (float*)d_out;

    const int B = in_sizes[0] / 512;

    setup_all<<<17, 256>>>(fq, Wq, bq, Wk, bk, bv, Wo, bo, W_fp, b_fp);
    setup_fuse<<<25, 256>>>(W_ip, W_tp, Wc1, b_ip, b_tp, bc1);
    setup_conv<<<1024, 256>>>(W_ie, W_te);
    setup_conv2<<<1104, 256>>>(Wv, Wc2);

    cudaFuncSetAttribute(enc_kernel, cudaFuncAttributeMaxDynamicSharedMemorySize,
                         ENC_SMEM);
    enc_kernel<<<dim3(B / 64, 2), 256, ENC_SMEM>>>(img, txt, b_ie, b_te);

    cudaFuncSetAttribute(tail_mma, cudaFuncAttributeMaxDynamicSharedMemorySize,
                         TAIL_SMEM);
    tail_mma<<<B / 32, 256, TAIL_SMEM>>>(img, txt, bc1, bc2, out);
}

// round 14
// speedup vs baseline: 1.1475x; 1.1475x over previous
#include <cuda_runtime.h>
#include <cuda_bf16.h>
#include <math.h>

typedef unsigned long long u64;
typedef unsigned int u32;
typedef unsigned short u16;
typedef __nv_bfloat16 bf16;
#define BMAX 131072

#define MMA16816(c, a, b0_, b1_)                                              \
    asm volatile("mma.sync.aligned.m16n8k16.row.col.f32.bf16.bf16.f32 "       \
                 "{%0,%1,%2,%3},{%4,%5,%6,%7},{%8,%9},{%0,%1,%2,%3};"         \
                 : "+f"((c)[0]), "+f"((c)[1]), "+f"((c)[2]), "+f"((c)[3])     \
                 : "r"((a)[0]), "r"((a)[1]), "r"((a)[2]), "r"((a)[3]),        \
                   "r"(b0_), "r"(b1_))

__device__ __forceinline__ void splitf(float x, u16& h, u16& l) {
    bf16 hb = __float2bfloat16_rn(x);
    bf16 lb = __float2bfloat16_rn(x - __bfloat162float(hb));
    h = *(u16*)&hb; l = *(u16*)&lb;
}

// ------------------------------ device globals ------------------------------
__device__ float g_q[256];
__device__ float g_wk[4 * 256];
__device__ float g_ck[4];
__device__ float g_tmp[256];
__device__ float g_Wof[256 * 512];
__device__ float g_bof[512];
__device__ float g_W5c[3 * 256 * 256];   // [b][k][n]
__device__ float g_b5c[3 * 256];
__device__ float g_e0[(size_t)BMAX * 256];
__device__ float g_e1[(size_t)BMAX * 256];
__device__ u16   g_Wmh[2 * 256 * 512], g_Wml[2 * 256 * 512];   // enc W [mod][n][k]
__device__ u16   g_Wvh[256 * 256],     g_Wvl[256 * 256];       // Wv^T  [n][k]
__device__ u16   g_W5h[3 * 256 * 256], g_W5l[3 * 256 * 256];   // W5c^T [b][n][k]
__device__ u16   g_Wch[80 * 256],      g_Wcl[80 * 256];        // Wc2^T [n][k]

// ---------------------------- setup kernel 1 --------------------------------
__global__ void setup_all(const float* __restrict__ fq, const float* __restrict__ Wq,
                          const float* __restrict__ bq, const float* __restrict__ Wk,
                          const float* __restrict__ bk, const float* __restrict__ bv,
                          const float* __restrict__ Wo, const float* __restrict__ bo,
                          const float* __restrict__ Wfp, const float* __restrict__ bfp) {
    __shared__ float sA[64 * 65];
    int t = threadIdx.x;
    if (blockIdx.x == 0) {
        {
            float s = bq[t];
#pragma unroll 8
            for (int k = 0; k < 256; k++) s = fmaf(fq[k], Wq[k * 256 + t], s);
            g_q[t] = s;
        }
        __syncthreads();
#pragma unroll
        for (int l = 0; l < 4; l++) {
            int idx = t + l * 256;
            int h = idx >> 8, j = idx & 255;
            float s = 0.f;
#pragma unroll 8
            for (int d = 0; d < 64; d++)
                s = fmaf(Wk[j * 256 + h * 64 + d], g_q[h * 64 + d], s);
            g_wk[h * 256 + j] = s;
        }
        if (t < 4) {
            float c = 0.f;
#pragma unroll 8
            for (int d = 0; d < 64; d++) c = fmaf(bk[t * 64 + d], g_q[t * 64 + d], c);
            g_ck[t] = c;
        }
        __syncthreads();
        {
            float s = bo[t];
#pragma unroll 8
            for (int k = 0; k < 256; k++) s = fmaf(bv[k], Wo[k * 256 + t], s);
            g_tmp[t] = s;
        }
        __syncthreads();
#pragma unroll
        for (int l = 0; l < 2; l++) {
            int j = t + l * 256;
            float s = bfp[j];
#pragma unroll 8
            for (int m = 0; m < 256; m++) s = fmaf(g_tmp[m], Wfp[m * 512 + j], s);
            g_bof[j] = s;
        }
        return;
    }
    int bid = blockIdx.x - 1;
    int tx = t & 31, ty = t >> 5;
    int it = bid >> 2, jt = bid & 3;
    float acc[8][4];
#pragma unroll
    for (int i = 0; i < 8; i++)
#pragma unroll
        for (int c = 0; c < 4; c++) acc[i][c] = 0.f;
    for (int mc = 0; mc < 256; mc += 64) {
        __syncthreads();
#pragma unroll
        for (int l = 0; l < 16; l++) {
            int idx = t + l * 256;
            int r = idx >> 6, k = idx & 63;
            sA[r * 65 + k] = Wo[(it * 64 + r) * 256 + mc + k];
        }
        __syncthreads();
#pragma unroll 2
        for (int k = 0; k < 64; k++) {
            const float* Wp = Wfp + (size_t)(mc + k) * 512 + jt * 128 + tx;
            float w[4];
#pragma unroll
            for (int c = 0; c < 4; c++) w[c] = Wp[c * 32];
#pragma unroll
            for (int i = 0; i < 8; i++) {
                float a = sA[(ty * 8 + i) * 65 + k];
#pragma unroll
                for (int c = 0; c < 4; c++) acc[i][c] = fmaf(a, w[c], acc[i][c]);
            }
        }
    }
    __syncthreads();
#pragma unroll
    for (int i = 0; i < 8; i++)
#pragma unroll
        for (int c = 0; c < 4; c++)
            g_Wof[(size_t)(it * 64 + ty * 8 + i) * 512 + jt * 128 + tx + 32 * c] =
                acc[i][c];
}

// ---------------------------- setup kernel 2 --------------------------------
__global__ void setup_fuse(const float* __restrict__ Wip, const float* __restrict__ Wtp,
                           const float* __restrict__ Wc1, const float* __restrict__ bip,
                           const float* __restrict__ btp, const float* __restrict__ bc1) {
    __shared__ float sA[64 * 65];
    int t = threadIdx.x;
    if (blockIdx.x == 24) {
#pragma unroll
        for (int b = 0; b < 3; b++) {
            const float* b5 = (b == 0) ? g_bof : (b == 1) ? bip : btp;
            float s = bc1[t];
#pragma unroll 8
            for (int m = 0; m < 512; m++) s = fmaf(b5[m], Wc1[m * 256 + t], s);
            g_b5c[b * 256 + t] = s;
        }
        return;
    }
    int b = blockIdx.x >> 3, bid = blockIdx.x & 7;
    int it = bid >> 1, jt = bid & 1;
    const float* A = (b == 0) ? g_Wof : (b == 1) ? Wip : Wtp;
    int tx = t & 31, ty = t >> 5;
    float acc[8][4];
#pragma unroll
    for (int i = 0; i < 8; i++)
#pragma unroll
        for (int c = 0; c < 4; c++) acc[i][c] = 0.f;
    for (int mc = 0; mc < 512; mc += 64) {
        __syncthreads();
#pragma unroll
        for (int l = 0; l < 16; l++) {
            int idx = t + l * 256;
            int r = idx >> 6, k = idx & 63;
            sA[r * 65 + k] = A[(size_t)(it * 64 + r) * 512 + mc + k];
        }
        __syncthreads();
#pragma unroll 2
        for (int m = 0; m < 64; m++) {
            const float* Wp = Wc1 + (size_t)(mc + m) * 256 + jt * 128 + tx;
            float w[4];
#pragma unroll
            for (int c = 0; c < 4; c++) w[c] = Wp[c * 32];
#pragma unroll
            for (int i = 0; i < 8; i++) {
                float a = sA[(ty * 8 + i) * 65 + m];
#pragma unroll
                for (int c = 0; c < 4; c++) acc[i][c] = fmaf(a, w[c], acc[i][c]);
            }
        }
    }
    __syncthreads();
#pragma unroll
    for (int i = 0; i < 8; i++)
#pragma unroll
        for (int c = 0; c < 4; c++)
            g_W5c[(size_t)b * 65536 + (size_t)(it * 64 + ty * 8 + i) * 256 +
                  jt * 128 + tx + 32 * c] = acc[i][c];
}

// ---------------- setup 3/4: split-convert weights ----------------
__global__ void setup_conv(const float* __restrict__ Wie, const float* __restrict__ Wte) {
    int idx = blockIdx.x * 256 + threadIdx.x;
    int mod = idx >> 17, loc = idx & 131071;
    int n = loc >> 9, k = loc & 511;
    const float* W = mod ? Wte : Wie;
    u16 h, l;
    splitf(W[(size_t)k * 256 + n], h, l);
    size_t o = (size_t)mod * 131072 + (size_t)n * 512 + k;
    g_Wmh[o] = h; g_Wml[o] = l;
}
__global__ void setup_conv2(const float* __restrict__ Wv, const float* __restrict__ Wc2) {
    int idx = blockIdx.x * 256 + threadIdx.x;
    u16 h, l;
    if (idx < 65536) {
        int n = idx >> 8, k = idx & 255;
        splitf(Wv[k * 256 + n], h, l);
        g_Wvh[n * 256 + k] = h; g_Wvl[n * 256 + k] = l;
    } else if (idx < 262144) {
        int t = idx - 65536, b = t >> 16, r = t & 65535;
        int n = r >> 8, k = r & 255;
        splitf(g_W5c[b * 65536 + k * 256 + n], h, l);
        g_W5h[b * 65536 + n * 256 + k] = h; g_W5l[b * 65536 + n * 256 + k] = l;
    } else if (idx < 282624) {
        int t = idx - 262144, n = t >> 8, k = t & 255;
        splitf(Wc2[k * 80 + n], h, l);
        g_Wch[n * 256 + k] = h; g_Wcl[n * 256 + k] = l;
    }
}

// ------------------- encoder kernel (HMMA, unchanged) -----------------------
#define ENC_STRIDE 264
#define ENC_SMEM (2 * 64 * ENC_STRIDE * 2)

__global__ void __launch_bounds__(256, 2)
enc_kernel(const float* __restrict__ img, const float* __restrict__ txt,
           const float* __restrict__ b_ie, const float* __restrict__ b_te) {
    extern __shared__ u16 smh[];
    u16* Ah = smh;
    u16* Al = smh + 64 * ENC_STRIDE;
    const int tid = threadIdx.x;
    const int lane = tid & 31, w = tid >> 5;
    const int g = lane >> 2, tig = lane & 3;
    const int mod = blockIdx.y;
    const size_t row0 = (size_t)blockIdx.x * 64;
    const float* X  = mod ? txt : img;
    const float* bb = mod ? b_te : b_ie;
    const u16* Wh = g_Wmh + (size_t)mod * 131072;
    const u16* Wl = g_Wml + (size_t)mod * 131072;
    float* eP = mod ? g_e1 : g_e0;
    float acc[2][8][4] = {};

    for (int kc = 0; kc < 512; kc += 256) {
        __syncthreads();
#pragma unroll
        for (int l = 0; l < 16; l++) {
            int idx = tid + l * 256;
            int r = idx >> 6, k4 = idx & 63;
            float4 v = *(const float4*)(X + (row0 + r) * 512 + kc + k4 * 4);
            u16 h[4], lo[4];
            splitf(v.x, h[0], lo[0]); splitf(v.y, h[1], lo[1]);
            splitf(v.z, h[2], lo[2]); splitf(v.w, h[3], lo[3]);
            u32 base = r * ENC_STRIDE + k4 * 4;
            *(u32*)(Ah + base)     = (u32)h[0] | ((u32)h[1] << 16);
            *(u32*)(Ah + base + 2) = (u32)h[2] | ((u32)h[3] << 16);
            *(u32*)(Al + base)     = (u32)lo[0] | ((u32)lo[1] << 16);
            *(u32*)(Al + base + 2) = (u32)lo[2] | ((u32)lo[3] << 16);
        }
        __syncthreads();
#pragma unroll 2
        for (int ks = 0; ks < 16; ks++) {
            int kof = kc + ks * 16;
            u32 ah[2][4], al[2][4];
#pragma unroll
            for (int mt = 0; mt < 2; mt++) {
                int m = w * 32 + mt * 16 + g;
                size_t o0 = (size_t)m * 512 + kof + 2 * tig, o8 = o0 + 8 * 512;
                ah[mt][0] = *(const u32*)(Wh + o0); ah[mt][1] = *(const u32*)(Wh + o8);
                ah[mt][2] = *(const u32*)(Wh + o0 + 8); ah[mt][3] = *(const u32*)(Wh + o8 + 8);
                al[mt][0] = *(const u32*)(Wl + o0); al[mt][1] = *(const u32*)(Wl + o8);
                al[mt][2] = *(const u32*)(Wl + o0 + 8); al[mt][3] = *(const u32*)(Wl + o8 + 8);
            }
            int ko = ks * 16;
#pragma unroll
            for (int nt = 0; nt < 8; nt++) {
                const u16* ar  = Ah + (nt * 8 + g) * ENC_STRIDE + ko;
                const u16* arl = Al + (nt * 8 + g) * ENC_STRIDE + ko;
                u32 bh0 = *(const u32*)(ar + 2 * tig);
                u32 bh1 = *(const u32*)(ar + 2 * tig + 8);
                u32 bl0 = *(const u32*)(arl + 2 * tig);
                u32 bl1 = *(const u32*)(arl + 2 * tig + 8);
#pragma unroll
                for (int mt = 0; mt < 2; mt++) {
                    MMA16816(acc[mt][nt], ah[mt], bh0, bh1);
                    MMA16816(acc[mt][nt], ah[mt], bl0, bl1);
                    MMA16816(acc[mt][nt], al[mt], bh0, bh1);
                }
            }
        }
    }
#pragma unroll
    for (int mt = 0; mt < 2; mt++) {
        int m0 = w * 32 + mt * 16 + g;
        float b0 = bb[m0], b8 = bb[m0 + 8];
#pragma unroll
        for (int nt = 0; nt < 8; nt++) {
            size_t r0 = row0 + nt * 8 + 2 * tig;
            float v;
            v = acc[mt][nt][0] + b0; eP[r0 * 256 + m0]           = v > 0.f ? v : 0.f;
            v = acc[mt][nt][1] + b0; eP[(r0 + 1) * 256 + m0]     = v > 0.f ? v : 0.f;
            v = acc[mt][nt][2] + b8; eP[r0 * 256 + m0 + 8]       = v > 0.f ? v : 0.f;
            v = acc[mt][nt][3] + b8; eP[(r0 + 1) * 256 + m0 + 8] = v > 0.f ? v : 0.f;
        }
    }
}

// --------------------------- tail kernel (HMMA) -----------------------------
// 32 rows/CTA (sorted), 256 threads, 2 CTAs/SM. Split-bf16 smem planes.
// GEMM1: q0=e0@Wv, q1=e1@Wv (mt-outer, unrolled nt, uniform guards),
// lerp epilogue -> xs. GEMM2: branch W5c -> h1. GEMM3: Wc2 -> out.
#define SR 264
#define T_E0H 0
#define T_E0L 8448
#define T_E1H 16896
#define T_E1L 25344
#define T_XSH 33792
#define T_XSL 42240
#define T_FLT 50688
#define TAIL_SMEM 102400

__global__ void __launch_bounds__(256, 2)
tail_mma(const float* __restrict__ img, const float* __restrict__ txt,
         const float* __restrict__ bc1, const float* __restrict__ bc2,
         float* __restrict__ out) {
    extern __shared__ u16 sh[];
    u16* E0H = sh + T_E0H; u16* E0L = sh + T_E0L;
    u16* E1H = sh + T_E1H; u16* E1L = sh + T_E1L;
    u16* XSH = sh + T_XSH; u16* XSL = sh + T_XSL;
    float* sattn = (float*)(sh + T_FLT);
    int* sflag = (int*)(sattn + 128);
    int* sperm = sflag + 32;
    int* ssbr  = sperm + 32;
    int* snb   = ssbr + 32;
    float* scratch = (float*)(sh + T_XSH);  // overlays xs (dead until GEMM1 epi)

    const int tid = threadIdx.x, lane = tid & 31, w = tid >> 5;
    const int g = lane >> 2, tig = lane & 3;
    const size_t row0 = (size_t)blockIdx.x * 32;

    // P0: flags + sort
    for (int l = 0; l < 2; l++) {
        int task = tid + l * 256;
        int mod = task >> 8, r = (task >> 3) & 31, p = task & 7;
        const float* X = mod ? txt : img;
        const float4* xp = (const float4*)(X + (row0 + r) * 512 + p * 64);
        float s = 0.f;
#pragma unroll
        for (int u = 0; u < 16; u++) {
            float4 v = xp[u];
            s += v.x * v.x + v.y * v.y + v.z * v.z + v.w * v.w;
        }
        scratch[task] = s;
    }
    __syncthreads();
    if (tid < 32) {
        float si = 0.f, st = 0.f;
#pragma unroll
        for (int p = 0; p < 8; p++) { si += scratch[tid * 8 + p]; st += scratch[256 + tid * 8 + p]; }
        int fi = si > 1e-12f, ft = st > 1e-12f;
        sflag[tid] = (fi && ft) ? 1 : (fi ? 2 : (ft ? 3 : 0));
    }
    __syncthreads();
    if (tid == 0) {
        int cnt[4] = {0, 0, 0, 0};
        for (int r = 0; r < 32; r++) cnt[sflag[r]]++;
        int base[4];
        base[1] = 0; base[2] = cnt[1]; base[3] = cnt[1] + cnt[2]; base[0] = base[3] + cnt[3];
        for (int r = 0; r < 32; r++) {
            int f = sflag[r], s = base[f]++;
            sperm[s] = r; ssbr[s] = f;
        }
        *snb = cnt[1];
    }
    __syncthreads();

    // P1: stage e0/e1 split-bf16 (sorted) + per-head dot partials
    {
        int s = tid >> 3, p = tid & 7;
        size_t gr = row0 + sperm[s];
        int k0 = p * 32;
        float d[2][4] = {};
        for (int m2 = 0; m2 < 2; m2++) {
            const float* src = (m2 ? g_e1 : g_e0) + gr * 256 + k0;
            u16* PH = m2 ? E1H : E0H;
            u16* PL = m2 ? E1L : E0L;
#pragma unroll
            for (int q = 0; q < 8; q++) {
                float4 v = *(const float4*)(src + q * 4);
                float vv[4] = {v.x, v.y, v.z, v.w};
#pragma unroll
                for (int e = 0; e < 4; e++) {
                    int k = k0 + q * 4 + e;
                    u16 hh, ll;
                    splitf(vv[e], hh, ll);
                    PH[s * SR + k] = hh; PL[s * SR + k] = ll;
#pragma unroll
                    for (int h = 0; h < 4; h++) d[m2][h] = fmaf(vv[e], g_wk[h * 256 + k], d[m2][h]);
                }
            }
        }
#pragma unroll
        for (int h = 0; h < 4; h++) {
            scratch[(s * 8 + p) * 4 + h] = d[0][h];
            scratch[1024 + (s * 8 + p) * 4 + h] = d[1][h];
        }
    }
    __syncthreads();
    if (tid < 128) {
        int s = tid >> 2, h = tid & 3;
        float d0 = 0.f, d1 = 0.f;
#pragma unroll
        for (int p = 0; p < 8; p++) {
            d0 += scratch[(s * 8 + p) * 4 + h];
            d1 += scratch[1024 + (s * 8 + p) * 4 + h];
        }
        float s0 = (d0 + g_ck[h]) * 0.125f, s1 = (d1 + g_ck[h]) * 0.125f;
        float m = fmaxf(s0, s1);
        float e0 = expf(s0 - m), e1 = expf(s1 - m);
        sattn[s * 4 + h] = e0 / (e0 + e1);
    }
    __syncthreads();
    const int nb = *snb;

    // GEMM1: q0=e0@Wv, q1=e1@Wv (mt outer, fully unrolled); lerp epi -> xs
    if (nb > 0) {
        int h = w >> 1, cw = w * 32;
#pragma unroll
        for (int mt = 0; mt < 2; mt++) {
            float q0a[4][4] = {}, q1a[4][4] = {};
            const int m = cw + mt * 16 + g;
            for (int ks = 0; ks < 16; ks++) {
                size_t o = (size_t)m * 256 + ks * 16 + 2 * tig, o8 = o + 2048;
                u32 ah[4] = {*(const u32*)(g_Wvh + o), *(const u32*)(g_Wvh + o8),
                             *(const u32*)(g_Wvh + o + 8), *(const u32*)(g_Wvh + o8 + 8)};
                u32 al[4] = {*(const u32*)(g_Wvl + o), *(const u32*)(g_Wvl + o8),
                             *(const u32*)(g_Wvl + o + 8), *(const u32*)(g_Wvl + o8 + 8)};
#pragma unroll
                for (int nt = 0; nt < 4; nt++) {
                    if (nt * 8 < nb) {
                        int base = (nt * 8 + g) * SR + ks * 16 + 2 * tig;
                        u32 x0h0 = *(const u32*)(E0H + base), x0h1 = *(const u32*)(E0H + base + 8);
                        u32 x0l0 = *(const u32*)(E0L + base), x0l1 = *(const u32*)(E0L + base + 8);
                        u32 x1h0 = *(const u32*)(E1H + base), x1h1 = *(const u32*)(E1H + base + 8);
                        u32 x1l0 = *(const u32*)(E1L + base), x1l1 = *(const u32*)(E1L + base + 8);
                        MMA16816(q0a[nt], ah, x0h0, x0h1);
                        MMA16816(q0a[nt], ah, x0l0, x0l1);
                        MMA16816(q0a[nt], al, x0h0, x0h1);
                        MMA16816(q1a[nt], ah, x1h0, x1h1);
                        MMA16816(q1a[nt], ah, x1l0, x1l1);
                        MMA16816(q1a[nt], al, x1h0, x1h1);
                    }
                }
            }
#pragma unroll
            for (int nt = 0; nt < 4; nt++) {
                if (nt * 8 < nb) {
                    int r0 = nt * 8 + 2 * tig;
#pragma unroll
                    for (int pr = 0; pr < 2; pr++) {
                        int r = r0 + pr;
                        if (r < nb) {
                            float a0 = sattn[r * 4 + h];
                            float v0 = fmaf(a0, q0a[nt][pr] - q1a[nt][pr], q1a[nt][pr]);
                            float v8 = fmaf(a0, q0a[nt][2 + pr] - q1a[nt][2 + pr],
                                            q1a[nt][2 + pr]);
                            u16 hh, ll;
                            splitf(v0, hh, ll); XSH[r * SR + m] = hh;     XSL[r * SR + m] = ll;
                            splitf(v8, hh, ll); XSH[r * SR + m + 8] = hh; XSL[r * SR + m + 8] = ll;
                        }
                    }
                }
            }
        }
    }
    __syncthreads();

    // P4: xs for non-both rows (copy e0/e1 or zero)
    for (int idx = tid; idx < 32 * 8; idx += 256) {
        int s = idx >> 3, q = idx & 7;
        if (s < nb) continue;
        int f = ssbr[s];
        uint4 z = make_uint4(0, 0, 0, 0);
#pragma unroll
        for (int j = 0; j < 4; j++) {
            uint4 vh = z, vl = z;
            if (f == 2) {
                vh = ((const uint4*)(E0H + s * SR))[q * 4 + j];
                vl = ((const uint4*)(E0L + s * SR))[q * 4 + j];
            } else if (f == 3) {
                vh = ((const uint4*)(E1H + s * SR))[q * 4 + j];
                vl = ((const uint4*)(E1L + s * SR))[q * 4 + j];
            }
            ((uint4*)(XSH + s * SR))[q * 4 + j] = vh;
            ((uint4*)(XSL + s * SR))[q * 4 + j] = vl;
        }
    }
    __syncthreads();

    // GEMM2: h1 = relu(xs @ W5c[branch] + bias) -> overlay e0 planes
    {
        int cw = w * 32;
        float a2[2][4][4] = {};
        for (int seg = 1; seg <= 3; seg++) {
            u32 ntm = 0;
            for (int i = 0; i < 32; i++)
                if (ssbr[i] == seg) ntm |= 1u << (i >> 3);
            if (!ntm) continue;
            const u16* WH = g_W5h + (size_t)(seg - 1) * 65536;
            const u16* WL = g_W5l + (size_t)(seg - 1) * 65536;
            for (int ks = 0; ks < 16; ks++) {
                u32 ah[2][4], al[2][4];
#pragma unroll
                for (int mt = 0; mt < 2; mt++) {
                    int m = cw + mt * 16 + g;
                    size_t o = (size_t)m * 256 + ks * 16 + 2 * tig, o8 = o + 2048;
                    ah[mt][0] = *(const u32*)(WH + o); ah[mt][1] = *(const u32*)(WH + o8);
                    ah[mt][2] = *(const u32*)(WH + o + 8); ah[mt][3] = *(const u32*)(WH + o8 + 8);
                    al[mt][0] = *(const u32*)(WL + o); al[mt][1] = *(const u32*)(WL + o8);
                    al[mt][2] = *(const u32*)(WL + o + 8); al[mt][3] = *(const u32*)(WL + o8 + 8);
                }
#pragma unroll
                for (int nt = 0; nt < 4; nt++) {
                    if (!((ntm >> nt) & 1)) continue;
                    int s = nt * 8 + g;
                    bool on = (ssbr[s] == seg);
                    int base = s * SR + ks * 16 + 2 * tig;
                    u32 bh0 = 0, bh1 = 0, bl0 = 0, bl1 = 0;
                    if (on) {
                        bh0 = *(const u32*)(XSH + base); bh1 = *(const u32*)(XSH + base + 8);
                        bl0 = *(const u32*)(XSL + base); bl1 = *(const u32*)(XSL + base + 8);
                    }
#pragma unroll
                    for (int mt = 0; mt < 2; mt++) {
                        MMA16816(a2[mt][nt], ah[mt], bh0, bh1);
                        MMA16816(a2[mt][nt], ah[mt], bl0, bl1);
                        MMA16816(a2[mt][nt], al[mt], bh0, bh1);
                    }
                }
            }
        }
#pragma unroll
        for (int nt = 0; nt < 4; nt++)
#pragma unroll
            for (int mt = 0; mt < 2; mt++) {
                int r0 = nt * 8 + 2 * tig, m0 = cw + mt * 16 + g;
#pragma unroll
                for (int pr = 0; pr < 2; pr++) {
                    int r = r0 + pr;
                    int f = ssbr[r];
                    float b0 = f ? g_b5c[(f - 1) * 256 + m0] : bc1[m0];
                    float b8 = f ? g_b5c[(f - 1) * 256 + m0 + 8] : bc1[m0 + 8];
                    float v0 = a2[mt][nt][pr] + b0;     v0 = v0 > 0.f ? v0 : 0.f;
                    float v8 = a2[mt][nt][2 + pr] + b8; v8 = v8 > 0.f ? v8 : 0.f;
                    u16 hh, ll;
                    splitf(v0, hh, ll); E0H[r * SR + m0] = hh;     E0L[r * SR + m0] = ll;
                    splitf(v8, hh, ll); E0H[r * SR + m0 + 8] = hh; E0L[r * SR + m0 + 8] = ll;
                }
            }
    }
    __syncthreads();

    // GEMM3: out = h1 @ Wc2 + bc2 (warps 0..4, 16 cols each)
    if (w < 5) {
        float a3[4][4] = {};
        for (int ks = 0; ks < 16; ks++) {
            int m = w * 16 + g;
            size_t o = (size_t)m * 256 + ks * 16 + 2 * tig, o8 = o + 2048;
            u32 ah[4] = {*(const u32*)(g_Wch + o), *(const u32*)(g_Wch + o8),
                         *(const u32*)(g_Wch + o + 8), *(const u32*)(g_Wch + o8 + 8)};
            u32 al[4] = {*(const u32*)(g_Wcl + o), *(const u32*)(g_Wcl + o8),
                         *(const u32*)(g_Wcl + o + 8), *(const u32*)(g_Wcl + o8 + 8)};
#pragma unroll
            for (int nt = 0; nt < 4; nt++) {
                int base = (nt * 8 + g) * SR + ks * 16 + 2 * tig;
                u32 bh0 = *(const u32*)(E0H + base), bh1 = *(const u32*)(E0H + base + 8);
                u32 bl0 = *(const u32*)(E0L + base), bl1 = *(const u32*)(E0L + base + 8);
                MMA16816(a3[nt], ah, bh0, bh1);
                MMA16816(a3[nt], ah, bl0, bl1);
                MMA16816(a3[nt], al, bh0, bh1);
            }
        }
#pragma unroll
        for (int nt = 0; nt < 4; nt++) {
            int r0 = nt * 8 + 2 * tig, m0 = w * 16 + g;
#pragma unroll
            for (int pr = 0; pr < 2; pr++) {
                size_t ro = (row0 + sperm[r0 + pr]) * 80;
                out[ro + m0]     = a3[nt][pr] + bc2[m0];
                out[ro + m0 + 8] = a3[nt][2 + pr] + bc2[m0 + 8];
            }
        }
    }
}

// ------------------------------- launch ------------------------------------
extern "C" void kernel_launch(void* const* d_in, const int* in_sizes, int n_in,
                              void* d_out, int out_size) {
    const float* img  = (const float*)d_in[0];
    const float* txt  = (const float*)d_in[1];
    const float* W_ie = (const float*)d_in[2];
    const float* b_ie = (const float*)d_in[3];
    const float* W_te = (const float*)d_in[4];
    const float* b_te = (const float*)d_in[5];
    const float* fq   = (const float*)d_in[6];
    const float* Wq   = (const float*)d_in[7];
    const float* bq   = (const float*)d_in[8];
    const float* Wk   = (const float*)d_in[9];
    const float* bk   = (const float*)d_in[10];
    const float* Wv   = (const float*)d_in[11];
    const float* bv   = (const float*)d_in[12];
    const float* Wo   = (const float*)d_in[13];
    const float* bo   = (const float*)d_in[14];
    const float* W_ip = (const float*)d_in[15];
    const float* b_ip = (const float*)d_in[16];
    const float* W_tp = (const float*)d_in[17];
    const float* b_tp = (const float*)d_in[18];
    const float* W_fp = (const float*)d_in[19];
    const float* b_fp = (const float*)d_in[20];
    const float* Wc1  = (const float*)d_in[21];
    const float* bc1  = (const float*)d_in[22];
    const float* Wc2  = (const float*)d_in[23];
    const float* bc2  = (const float*)d_in[24];
    float* out = (float*)d_out;

    const int B = in_sizes[0] / 512;

    setup_all<<<17, 256>>>(fq, Wq, bq, Wk, bk, bv, Wo, bo, W_fp, b_fp);
    setup_fuse<<<25, 256>>>(W_ip, W_tp, Wc1, b_ip, b_tp, bc1);
    setup_conv<<<1024, 256>>>(W_ie, W_te);
    setup_conv2<<<1104, 256>>>(Wv, Wc2);

    cudaFuncSetAttribute(enc_kernel, cudaFuncAttributeMaxDynamicSharedMemorySize,
                         ENC_SMEM);
    enc_kernel<<<dim3(B / 64, 2), 256, ENC_SMEM>>>(img, txt, b_ie, b_te);

    cudaFuncSetAttribute(tail_mma, cudaFuncAttributeMaxDynamicSharedMemorySize,
                         TAIL_SMEM);
    tail_mma<<<B / 32, 256, TAIL_SMEM>>>(img, txt, bc1, bc2, out);
}

// round 15
// speedup vs baseline: 1.2557x; 1.0942x over previous
#include <cuda_runtime.h>
#include <cuda_bf16.h>
#include <math.h>

typedef unsigned long long u64;
typedef unsigned int u32;
typedef unsigned short u16;
typedef __nv_bfloat16 bf16;
#define BMAX 131072

#define MMA16816(c, a, b0_, b1_)                                              \
    asm volatile("mma.sync.aligned.m16n8k16.row.col.f32.bf16.bf16.f32 "       \
                 "{%0,%1,%2,%3},{%4,%5,%6,%7},{%8,%9},{%0,%1,%2,%3};"         \
                 : "+f"((c)[0]), "+f"((c)[1]), "+f"((c)[2]), "+f"((c)[3])     \
                 : "r"((a)[0]), "r"((a)[1]), "r"((a)[2]), "r"((a)[3]),        \
                   "r"(b0_), "r"(b1_))

__device__ __forceinline__ void splitf(float x, u16& h, u16& l) {
    bf16 hb = __float2bfloat16_rn(x);
    bf16 lb = __float2bfloat16_rn(x - __bfloat162float(hb));
    h = *(u16*)&hb; l = *(u16*)&lb;
}
__device__ __forceinline__ u32 packsplit(float x) {
    u16 h, l;
    splitf(x, h, l);
    return (u32)h | ((u32)l << 16);
}

// ------------------------------ device globals ------------------------------
__device__ float g_q[256];
__device__ float g_wk[4 * 256];
__device__ float g_ck[4];
__device__ float g_tmp[256];
__device__ float g_Wof[256 * 512];
__device__ float g_bof[512];
__device__ float g_W5c[3 * 256 * 256];   // [b][k][n]
__device__ float g_b5c[3 * 256];
__device__ u32   g_ep0[(size_t)BMAX * 256];  // enc_img split pair (hi | lo<<16)
__device__ u32   g_ep1[(size_t)BMAX * 256];  // enc_txt split pair
__device__ int   g_fi[BMAX], g_ft[BMAX];
__device__ u16   g_Wmh[2 * 256 * 512], g_Wml[2 * 256 * 512];   // enc W [mod][n][k]
__device__ u16   g_Wvh[256 * 256],     g_Wvl[256 * 256];       // Wv^T  [n][k]
__device__ u16   g_W5h[3 * 256 * 256], g_W5l[3 * 256 * 256];   // W5c^T [b][n][k]
__device__ u16   g_Wch[80 * 256],      g_Wcl[80 * 256];        // Wc2^T [n][k]

// ---------------------------- setup kernel 1 --------------------------------
__global__ void setup_all(const float* __restrict__ fq, const float* __restrict__ Wq,
                          const float* __restrict__ bq, const float* __restrict__ Wk,
                          const float* __restrict__ bk, const float* __restrict__ bv,
                          const float* __restrict__ Wo, const float* __restrict__ bo,
                          const float* __restrict__ Wfp, const float* __restrict__ bfp) {
    __shared__ float sA[64 * 65];
    int t = threadIdx.x;
    if (blockIdx.x == 0) {
        {
            float s = bq[t];
#pragma unroll 8
            for (int k = 0; k < 256; k++) s = fmaf(fq[k], Wq[k * 256 + t], s);
            g_q[t] = s;
        }
        __syncthreads();
#pragma unroll
        for (int l = 0; l < 4; l++) {
            int idx = t + l * 256;
            int h = idx >> 8, j = idx & 255;
            float s = 0.f;
#pragma unroll 8
            for (int d = 0; d < 64; d++)
                s = fmaf(Wk[j * 256 + h * 64 + d], g_q[h * 64 + d], s);
            g_wk[h * 256 + j] = s;
        }
        if (t < 4) {
            float c = 0.f;
#pragma unroll 8
            for (int d = 0; d < 64; d++) c = fmaf(bk[t * 64 + d], g_q[t * 64 + d], c);
            g_ck[t] = c;
        }
        __syncthreads();
        {
            float s = bo[t];
#pragma unroll 8
            for (int k = 0; k < 256; k++) s = fmaf(bv[k], Wo[k * 256 + t], s);
            g_tmp[t] = s;
        }
        __syncthreads();
#pragma unroll
        for (int l = 0; l < 2; l++) {
            int j = t + l * 256;
            float s = bfp[j];
#pragma unroll 8
            for (int m = 0; m < 256; m++) s = fmaf(g_tmp[m], Wfp[m * 512 + j], s);
            g_bof[j] = s;
        }
        return;
    }
    int bid = blockIdx.x - 1;
    int tx = t & 31, ty = t >> 5;
    int it = bid >> 2, jt = bid & 3;
    float acc[8][4];
#pragma unroll
    for (int i = 0; i < 8; i++)
#pragma unroll
        for (int c = 0; c < 4; c++) acc[i][c] = 0.f;
    for (int mc = 0; mc < 256; mc += 64) {
        __syncthreads();
#pragma unroll
        for (int l = 0; l < 16; l++) {
            int idx = t + l * 256;
            int r = idx >> 6, k = idx & 63;
            sA[r * 65 + k] = Wo[(it * 64 + r) * 256 + mc + k];
        }
        __syncthreads();
#pragma unroll 2
        for (int k = 0; k < 64; k++) {
            const float* Wp = Wfp + (size_t)(mc + k) * 512 + jt * 128 + tx;
            float w[4];
#pragma unroll
            for (int c = 0; c < 4; c++) w[c] = Wp[c * 32];
#pragma unroll
            for (int i = 0; i < 8; i++) {
                float a = sA[(ty * 8 + i) * 65 + k];
#pragma unroll
                for (int c = 0; c < 4; c++) acc[i][c] = fmaf(a, w[c], acc[i][c]);
            }
        }
    }
    __syncthreads();
#pragma unroll
    for (int i = 0; i < 8; i++)
#pragma unroll
        for (int c = 0; c < 4; c++)
            g_Wof[(size_t)(it * 64 + ty * 8 + i) * 512 + jt * 128 + tx + 32 * c] =
                acc[i][c];
}

// ---------------------------- setup kernel 2 --------------------------------
__global__ void setup_fuse(const float* __restrict__ Wip, const float* __restrict__ Wtp,
                           const float* __restrict__ Wc1, const float* __restrict__ bip,
                           const float* __restrict__ btp, const float* __restrict__ bc1) {
    __shared__ float sA[64 * 65];
    int t = threadIdx.x;
    if (blockIdx.x == 24) {
#pragma unroll
        for (int b = 0; b < 3; b++) {
            const float* b5 = (b == 0) ? g_bof : (b == 1) ? bip : btp;
            float s = bc1[t];
#pragma unroll 8
            for (int m = 0; m < 512; m++) s = fmaf(b5[m], Wc1[m * 256 + t], s);
            g_b5c[b * 256 + t] = s;
        }
        return;
    }
    int b = blockIdx.x >> 3, bid = blockIdx.x & 7;
    int it = bid >> 1, jt = bid & 1;
    const float* A = (b == 0) ? g_Wof : (b == 1) ? Wip : Wtp;
    int tx = t & 31, ty = t >> 5;
    float acc[8][4];
#pragma unroll
    for (int i = 0; i < 8; i++)
#pragma unroll
        for (int c = 0; c < 4; c++) acc[i][c] = 0.f;
    for (int mc = 0; mc < 512; mc += 64) {
        __syncthreads();
#pragma unroll
        for (int l = 0; l < 16; l++) {
            int idx = t + l * 256;
            int r = idx >> 6, k = idx & 63;
            sA[r * 65 + k] = A[(size_t)(it * 64 + r) * 512 + mc + k];
        }
        __syncthreads();
#pragma unroll 2
        for (int m = 0; m < 64; m++) {
            const float* Wp = Wc1 + (size_t)(mc + m) * 256 + jt * 128 + tx;
            float w[4];
#pragma unroll
            for (int c = 0; c < 4; c++) w[c] = Wp[c * 32];
#pragma unroll
            for (int i = 0; i < 8; i++) {
                float a = sA[(ty * 8 + i) * 65 + m];
#pragma unroll
                for (int c = 0; c < 4; c++) acc[i][c] = fmaf(a, w[c], acc[i][c]);
            }
        }
    }
    __syncthreads();
#pragma unroll
    for (int i = 0; i < 8; i++)
#pragma unroll
        for (int c = 0; c < 4; c++)
            g_W5c[(size_t)b * 65536 + (size_t)(it * 64 + ty * 8 + i) * 256 +
                  jt * 128 + tx + 32 * c] = acc[i][c];
}

// ---------------- setup 3/4: split-convert weights ----------------
__global__ void setup_conv(const float* __restrict__ Wie, const float* __restrict__ Wte) {
    int idx = blockIdx.x * 256 + threadIdx.x;
    int mod = idx >> 17, loc = idx & 131071;
    int n = loc >> 9, k = loc & 511;
    const float* W = mod ? Wte : Wie;
    u16 h, l;
    splitf(W[(size_t)k * 256 + n], h, l);
    size_t o = (size_t)mod * 131072 + (size_t)n * 512 + k;
    g_Wmh[o] = h; g_Wml[o] = l;
}
__global__ void setup_conv2(const float* __restrict__ Wv, const float* __restrict__ Wc2) {
    int idx = blockIdx.x * 256 + threadIdx.x;
    u16 h, l;
    if (idx < 65536) {
        int n = idx >> 8, k = idx & 255;
        splitf(Wv[k * 256 + n], h, l);
        g_Wvh[n * 256 + k] = h; g_Wvl[n * 256 + k] = l;
    } else if (idx < 262144) {
        int t = idx - 65536, b = t >> 16, r = t & 65535;
        int n = r >> 8, k = r & 255;
        splitf(g_W5c[b * 65536 + k * 256 + n], h, l);
        g_W5h[b * 65536 + n * 256 + k] = h; g_W5l[b * 65536 + n * 256 + k] = l;
    } else if (idx < 282624) {
        int t = idx - 262144, n = t >> 8, k = t & 255;
        splitf(Wc2[k * 80 + n], h, l);
        g_Wch[n * 256 + k] = h; g_Wcl[n * 256 + k] = l;
    }
}

// -------- encoder kernel (HMMA) + flags + packed split-plane output --------
#define ENC_STRIDE 264
#define ENC_SQ (2 * 64 * ENC_STRIDE)          // u16 offset of sq scratch
#define ENC_SMEM (2 * 64 * ENC_STRIDE * 2 + 64 * 64 * 4)

__global__ void __launch_bounds__(256, 2)
enc_kernel(const float* __restrict__ img, const float* __restrict__ txt,
           const float* __restrict__ b_ie, const float* __restrict__ b_te) {
    extern __shared__ u16 smh[];
    u16* Ah = smh;
    u16* Al = smh + 64 * ENC_STRIDE;
    float* sq = (float*)(smh + ENC_SQ);       // [64][64]
    const int tid = threadIdx.x;
    const int lane = tid & 31, w = tid >> 5;
    const int g = lane >> 2, tig = lane & 3;
    const int mod = blockIdx.y;
    const size_t row0 = (size_t)blockIdx.x * 64;
    const float* X  = mod ? txt : img;
    const float* bb = mod ? b_te : b_ie;
    const u16* Wh = g_Wmh + (size_t)mod * 131072;
    const u16* Wl = g_Wml + (size_t)mod * 131072;
    u32* eP = mod ? g_ep1 : g_ep0;
    int* fP = mod ? g_ft : g_fi;
    float acc[2][8][4] = {};

    for (int kc = 0; kc < 512; kc += 256) {
        __syncthreads();
#pragma unroll
        for (int l = 0; l < 16; l++) {
            int idx = tid + l * 256;
            int r = idx >> 6, k4 = idx & 63;
            float4 v = *(const float4*)(X + (row0 + r) * 512 + kc + k4 * 4);
            float ss = v.x * v.x + v.y * v.y + v.z * v.z + v.w * v.w;
            if (kc == 0) sq[r * 64 + k4] = ss;
            else         sq[r * 64 + k4] += ss;
            u16 h[4], lo[4];
            splitf(v.x, h[0], lo[0]); splitf(v.y, h[1], lo[1]);
            splitf(v.z, h[2], lo[2]); splitf(v.w, h[3], lo[3]);
            u32 base = r * ENC_STRIDE + k4 * 4;
            *(u32*)(Ah + base)     = (u32)h[0] | ((u32)h[1] << 16);
            *(u32*)(Ah + base + 2) = (u32)h[2] | ((u32)h[3] << 16);
            *(u32*)(Al + base)     = (u32)lo[0] | ((u32)lo[1] << 16);
            *(u32*)(Al + base + 2) = (u32)lo[2] | ((u32)lo[3] << 16);
        }
        __syncthreads();
#pragma unroll 2
        for (int ks = 0; ks < 16; ks++) {
            int kof = kc + ks * 16;
            u32 ah[2][4], al[2][4];
#pragma unroll
            for (int mt = 0; mt < 2; mt++) {
                int m = w * 32 + mt * 16 + g;
                size_t o0 = (size_t)m * 512 + kof + 2 * tig, o8 = o0 + 8 * 512;
                ah[mt][0] = *(const u32*)(Wh + o0); ah[mt][1] = *(const u32*)(Wh + o8);
                ah[mt][2] = *(const u32*)(Wh + o0 + 8); ah[mt][3] = *(const u32*)(Wh + o8 + 8);
                al[mt][0] = *(const u32*)(Wl + o0); al[mt][1] = *(const u32*)(Wl + o8);
                al[mt][2] = *(const u32*)(Wl + o0 + 8); al[mt][3] = *(const u32*)(Wl + o8 + 8);
            }
            int ko = ks * 16;
#pragma unroll
            for (int nt = 0; nt < 8; nt++) {
                const u16* ar  = Ah + (nt * 8 + g) * ENC_STRIDE + ko;
                const u16* arl = Al + (nt * 8 + g) * ENC_STRIDE + ko;
                u32 bh0 = *(const u32*)(ar + 2 * tig);
                u32 bh1 = *(const u32*)(ar + 2 * tig + 8);
                u32 bl0 = *(const u32*)(arl + 2 * tig);
                u32 bl1 = *(const u32*)(arl + 2 * tig + 8);
#pragma unroll
                for (int mt = 0; mt < 2; mt++) {
                    MMA16816(acc[mt][nt], ah[mt], bh0, bh1);
                    MMA16816(acc[mt][nt], ah[mt], bl0, bl1);
                    MMA16816(acc[mt][nt], al[mt], bh0, bh1);
                }
            }
        }
    }
    // flags (sq complete after last staging sync)
    if (tid < 64) {
        float s = 0.f;
#pragma unroll 8
        for (int i = 0; i < 64; i++) s += sq[tid * 64 + i];
        fP[row0 + tid] = (s > 1e-12f) ? 1 : 0;
    }
    // epilogue: bias + relu -> packed split plane
#pragma unroll
    for (int mt = 0; mt < 2; mt++) {
        int m0 = w * 32 + mt * 16 + g;
        float b0 = bb[m0], b8 = bb[m0 + 8];
#pragma unroll
        for (int nt = 0; nt < 8; nt++) {
            size_t r0 = row0 + nt * 8 + 2 * tig;
            float v;
            v = acc[mt][nt][0] + b0; eP[r0 * 256 + m0]           = packsplit(v > 0.f ? v : 0.f);
            v = acc[mt][nt][1] + b0; eP[(r0 + 1) * 256 + m0]     = packsplit(v > 0.f ? v : 0.f);
            v = acc[mt][nt][2] + b8; eP[r0 * 256 + m0 + 8]       = packsplit(v > 0.f ? v : 0.f);
            v = acc[mt][nt][3] + b8; eP[(r0 + 1) * 256 + m0 + 8] = packsplit(v > 0.f ? v : 0.f);
        }
    }
}

// --------------------------- tail kernel (HMMA) -----------------------------
// 32 rows/CTA (sorted), 256 threads, 2 CTAs/SM. Split-bf16 smem planes.
#define SR 264
#define T_E0H 0
#define T_E0L 8448
#define T_E1H 16896
#define T_E1L 25344
#define T_XSH 33792
#define T_XSL 42240
#define T_FLT 50688
#define TAIL_SMEM 102400

__global__ void __launch_bounds__(256, 2)
tail_mma(const float* __restrict__ bc1, const float* __restrict__ bc2,
         float* __restrict__ out) {
    extern __shared__ u16 sh[];
    u16* E0H = sh + T_E0H; u16* E0L = sh + T_E0L;
    u16* E1H = sh + T_E1H; u16* E1L = sh + T_E1L;
    u16* XSH = sh + T_XSH; u16* XSL = sh + T_XSL;
    float* sattn = (float*)(sh + T_FLT);
    int* sflag = (int*)(sattn + 128);
    int* sperm = sflag + 32;
    int* ssbr  = sperm + 32;
    int* snb   = ssbr + 32;
    float* scratch = (float*)(sh + T_XSH);  // overlays xs (dead until GEMM1 epi)

    const int tid = threadIdx.x, lane = tid & 31, w = tid >> 5;
    const int g = lane >> 2, tig = lane & 3;
    const size_t row0 = (size_t)blockIdx.x * 32;

    // P0: flags (from enc) + sort
    if (tid < 32) {
        int fi = g_fi[row0 + tid], ft = g_ft[row0 + tid];
        sflag[tid] = (fi && ft) ? 1 : (fi ? 2 : (ft ? 3 : 0));
    }
    __syncthreads();
    if (tid == 0) {
        int cnt[4] = {0, 0, 0, 0};
        for (int r = 0; r < 32; r++) cnt[sflag[r]]++;
        int base[4];
        base[1] = 0; base[2] = cnt[1]; base[3] = cnt[1] + cnt[2]; base[0] = base[3] + cnt[3];
        for (int r = 0; r < 32; r++) {
            int f = sflag[r], s = base[f]++;
            sperm[s] = r; ssbr[s] = f;
        }
        *snb = cnt[1];
    }
    __syncthreads();

    // P1: unpack packed split planes (sorted) + per-head dot partials
    {
        int s = tid >> 3, p = tid & 7;
        size_t gr = row0 + sperm[s];
        int k0 = p * 32;
        float d[2][4] = {};
#pragma unroll
        for (int m2 = 0; m2 < 2; m2++) {
            const u32* src = (m2 ? g_ep1 : g_ep0) + gr * 256 + k0;
            u16* PH = m2 ? E1H : E0H;
            u16* PL = m2 ? E1L : E0L;
#pragma unroll
            for (int q = 0; q < 8; q++) {
                uint4 v = *(const uint4*)(src + q * 4);
                int k = k0 + q * 4;
                *(u32*)(PH + s * SR + k)     = (v.x & 0xffffu) | ((v.y & 0xffffu) << 16);
                *(u32*)(PH + s * SR + k + 2) = (v.z & 0xffffu) | ((v.w & 0xffffu) << 16);
                *(u32*)(PL + s * SR + k)     = (v.x >> 16) | (v.y & 0xffff0000u);
                *(u32*)(PL + s * SR + k + 2) = (v.z >> 16) | (v.w & 0xffff0000u);
                float e0 = __uint_as_float(v.x << 16) + __uint_as_float(v.x & 0xffff0000u);
                float e1 = __uint_as_float(v.y << 16) + __uint_as_float(v.y & 0xffff0000u);
                float e2 = __uint_as_float(v.z << 16) + __uint_as_float(v.z & 0xffff0000u);
                float e3 = __uint_as_float(v.w << 16) + __uint_as_float(v.w & 0xffff0000u);
#pragma unroll
                for (int h = 0; h < 4; h++) {
                    const float* wk = g_wk + h * 256 + k;
                    d[m2][h] = fmaf(e0, wk[0], d[m2][h]);
                    d[m2][h] = fmaf(e1, wk[1], d[m2][h]);
                    d[m2][h] = fmaf(e2, wk[2], d[m2][h]);
                    d[m2][h] = fmaf(e3, wk[3], d[m2][h]);
                }
            }
        }
#pragma unroll
        for (int h = 0; h < 4; h++) {
            scratch[(s * 8 + p) * 4 + h] = d[0][h];
            scratch[1024 + (s * 8 + p) * 4 + h] = d[1][h];
        }
    }
    __syncthreads();
    if (tid < 128) {
        int s = tid >> 2, h = tid & 3;
        float d0 = 0.f, d1 = 0.f;
#pragma unroll
        for (int p = 0; p < 8; p++) {
            d0 += scratch[(s * 8 + p) * 4 + h];
            d1 += scratch[1024 + (s * 8 + p) * 4 + h];
        }
        float s0 = (d0 + g_ck[h]) * 0.125f, s1 = (d1 + g_ck[h]) * 0.125f;
        float m = fmaxf(s0, s1);
        float e0 = expf(s0 - m), e1 = expf(s1 - m);
        sattn[s * 4 + h] = e0 / (e0 + e1);
    }
    __syncthreads();
    const int nb = *snb;

    // GEMM1: q0=e0@Wv, q1=e1@Wv (mt outer); lerp epilogue -> xs
    if (nb > 0) {
        int h = w >> 1, cw = w * 32;
#pragma unroll
        for (int mt = 0; mt < 2; mt++) {
            float q0a[4][4] = {}, q1a[4][4] = {};
            const int m = cw + mt * 16 + g;
            for (int ks = 0; ks < 16; ks++) {
                size_t o = (size_t)m * 256 + ks * 16 + 2 * tig, o8 = o + 2048;
                u32 ah[4] = {*(const u32*)(g_Wvh + o), *(const u32*)(g_Wvh + o8),
                             *(const u32*)(g_Wvh + o + 8), *(const u32*)(g_Wvh + o8 + 8)};
                u32 al[4] = {*(const u32*)(g_Wvl + o), *(const u32*)(g_Wvl + o8),
                             *(const u32*)(g_Wvl + o + 8), *(const u32*)(g_Wvl + o8 + 8)};
#pragma unroll
                for (int nt = 0; nt < 4; nt++) {
                    if (nt * 8 < nb) {
                        int base = (nt * 8 + g) * SR + ks * 16 + 2 * tig;
                        u32 x0h0 = *(const u32*)(E0H + base), x0h1 = *(const u32*)(E0H + base + 8);
                        u32 x0l0 = *(const u32*)(E0L + base), x0l1 = *(const u32*)(E0L + base + 8);
                        u32 x1h0 = *(const u32*)(E1H + base), x1h1 = *(const u32*)(E1H + base + 8);
                        u32 x1l0 = *(const u32*)(E1L + base), x1l1 = *(const u32*)(E1L + base + 8);
                        MMA16816(q0a[nt], ah, x0h0, x0h1);
                        MMA16816(q0a[nt], ah, x0l0, x0l1);
                        MMA16816(q0a[nt], al, x0h0, x0h1);
                        MMA16816(q1a[nt], ah, x1h0, x1h1);
                        MMA16816(q1a[nt], ah, x1l0, x1l1);
                        MMA16816(q1a[nt], al, x1h0, x1h1);
                    }
                }
            }
#pragma unroll
            for (int nt = 0; nt < 4; nt++) {
                if (nt * 8 < nb) {
                    int r0 = nt * 8 + 2 * tig;
#pragma unroll
                    for (int pr = 0; pr < 2; pr++) {
                        int r = r0 + pr;
                        if (r < nb) {
                            float a0 = sattn[r * 4 + h];
                            float v0 = fmaf(a0, q0a[nt][pr] - q1a[nt][pr], q1a[nt][pr]);
                            float v8 = fmaf(a0, q0a[nt][2 + pr] - q1a[nt][2 + pr],
                                            q1a[nt][2 + pr]);
                            u16 hh, ll;
                            splitf(v0, hh, ll); XSH[r * SR + m] = hh;     XSL[r * SR + m] = ll;
                            splitf(v8, hh, ll); XSH[r * SR + m + 8] = hh; XSL[r * SR + m + 8] = ll;
                        }
                    }
                }
            }
        }
    }
    __syncthreads();

    // P4: xs for non-both rows (copy e0/e1 or zero)
    for (int idx = tid; idx < 32 * 8; idx += 256) {
        int s = idx >> 3, q = idx & 7;
        if (s < nb) continue;
        int f = ssbr[s];
        uint4 z = make_uint4(0, 0, 0, 0);
#pragma unroll
        for (int j = 0; j < 4; j++) {
            uint4 vh = z, vl = z;
            if (f == 2) {
                vh = ((const uint4*)(E0H + s * SR))[q * 4 + j];
                vl = ((const uint4*)(E0L + s * SR))[q * 4 + j];
            } else if (f == 3) {
                vh = ((const uint4*)(E1H + s * SR))[q * 4 + j];
                vl = ((const uint4*)(E1L + s * SR))[q * 4 + j];
            }
            ((uint4*)(XSH + s * SR))[q * 4 + j] = vh;
            ((uint4*)(XSL + s * SR))[q * 4 + j] = vl;
        }
    }
    __syncthreads();

    // GEMM2: h1 = relu(xs @ W5c[branch] + bias) -> overlay e0 planes
    {
        int cw = w * 32;
        float a2[2][4][4] = {};
        for (int seg = 1; seg <= 3; seg++) {
            u32 ntm = 0;
            for (int i = 0; i < 32; i++)
                if (ssbr[i] == seg) ntm |= 1u << (i >> 3);
            if (!ntm) continue;
            const u16* WH = g_W5h + (size_t)(seg - 1) * 65536;
            const u16* WL = g_W5l + (size_t)(seg - 1) * 65536;
            for (int ks = 0; ks < 16; ks++) {
                u32 ah[2][4], al[2][4];
#pragma unroll
                for (int mt = 0; mt < 2; mt++) {
                    int m = cw + mt * 16 + g;
                    size_t o = (size_t)m * 256 + ks * 16 + 2 * tig, o8 = o + 2048;
                    ah[mt][0] = *(const u32*)(WH + o); ah[mt][1] = *(const u32*)(WH + o8);
                    ah[mt][2] = *(const u32*)(WH + o + 8); ah[mt][3] = *(const u32*)(WH + o8 + 8);
                    al[mt][0] = *(const u32*)(WL + o); al[mt][1] = *(const u32*)(WL + o8);
                    al[mt][2] = *(const u32*)(WL + o + 8); al[mt][3] = *(const u32*)(WL + o8 + 8);
                }
#pragma unroll
                for (int nt = 0; nt < 4; nt++) {
                    if (!((ntm >> nt) & 1)) continue;
                    int s = nt * 8 + g;
                    bool on = (ssbr[s] == seg);
                    int base = s * SR + ks * 16 + 2 * tig;
                    u32 bh0 = 0, bh1 = 0, bl0 = 0, bl1 = 0;
                    if (on) {
                        bh0 = *(const u32*)(XSH + base); bh1 = *(const u32*)(XSH + base + 8);
                        bl0 = *(const u32*)(XSL + base); bl1 = *(const u32*)(XSL + base + 8);
                    }
#pragma unroll
                    for (int mt = 0; mt < 2; mt++) {
                        MMA16816(a2[mt][nt], ah[mt], bh0, bh1);
                        MMA16816(a2[mt][nt], ah[mt], bl0, bl1);
                        MMA16816(a2[mt][nt], al[mt], bh0, bh1);
                    }
                }
            }
        }
#pragma unroll
        for (int nt = 0; nt < 4; nt++)
#pragma unroll
            for (int mt = 0; mt < 2; mt++) {
                int r0 = nt * 8 + 2 * tig, m0 = cw + mt * 16 + g;
#pragma unroll
                for (int pr = 0; pr < 2; pr++) {
                    int r = r0 + pr;
                    int f = ssbr[r];
                    float b0 = f ? g_b5c[(f - 1) * 256 + m0] : bc1[m0];
                    float b8 = f ? g_b5c[(f - 1) * 256 + m0 + 8] : bc1[m0 + 8];
                    float v0 = a2[mt][nt][pr] + b0;     v0 = v0 > 0.f ? v0 : 0.f;
                    float v8 = a2[mt][nt][2 + pr] + b8; v8 = v8 > 0.f ? v8 : 0.f;
                    u16 hh, ll;
                    splitf(v0, hh, ll); E0H[r * SR + m0] = hh;     E0L[r * SR + m0] = ll;
                    splitf(v8, hh, ll); E0H[r * SR + m0 + 8] = hh; E0L[r * SR + m0 + 8] = ll;
                }
            }
    }
    __syncthreads();

    // GEMM3: out = h1 @ Wc2 + bc2 (warps 0..4, 16 cols each)
    if (w < 5) {
        float a3[4][4] = {};
        for (int ks = 0; ks < 16; ks++) {
            int m = w * 16 + g;
            size_t o = (size_t)m * 256 + ks * 16 + 2 * tig, o8 = o + 2048;
            u32 ah[4] = {*(const u32*)(g_Wch + o), *(const u32*)(g_Wch + o8),
                         *(const u32*)(g_Wch + o + 8), *(const u32*)(g_Wch + o8 + 8)};
            u32 al[4] = {*(const u32*)(g_Wcl + o), *(const u32*)(g_Wcl + o8),
                         *(const u32*)(g_Wcl + o + 8), *(const u32*)(g_Wcl + o8 + 8)};
#pragma unroll
            for (int nt = 0; nt < 4; nt++) {
                int base = (nt * 8 + g) * SR + ks * 16 + 2 * tig;
                u32 bh0 = *(const u32*)(E0H + base), bh1 = *(const u32*)(E0H + base + 8);
                u32 bl0 = *(const u32*)(E0L + base), bl1 = *(const u32*)(E0L + base + 8);
                MMA16816(a3[nt], ah, bh0, bh1);
                MMA16816(a3[nt], ah, bl0, bl1);
                MMA16816(a3[nt], al, bh0, bh1);
            }
        }
#pragma unroll
        for (int nt = 0; nt < 4; nt++) {
            int r0 = nt * 8 + 2 * tig, m0 = w * 16 + g;
#pragma unroll
            for (int pr = 0; pr < 2; pr++) {
                size_t ro = (row0 + sperm[r0 + pr]) * 80;
                out[ro + m0]     = a3[nt][pr] + bc2[m0];
                out[ro + m0 + 8] = a3[nt][2 + pr] + bc2[m0 + 8];
            }
        }
    }
}

// ------------------------------- launch ------------------------------------
extern "C" void kernel_launch(void* const* d_in, const int* in_sizes, int n_in,
                              void* d_out, int out_size) {
    const float* img  = (const float*)d_in[0];
    const float* txt  = (const float*)d_in[1];
    const float* W_ie = (const float*)d_in[2];
    const float* b_ie = (const float*)d_in[3];
    const float* W_te = (const float*)d_in[4];
    const float* b_te = (const float*)d_in[5];
    const float* fq   = (const float*)d_in[6];
    const float* Wq   = (const float*)d_in[7];
    const float* bq   = (const float*)d_in[8];
    const float* Wk   = (const float*)d_in[9];
    const float* bk   = (const float*)d_in[10];
    const float* Wv   = (const float*)d_in[11];
    const float* bv   = (const float*)d_in[12];
    const float* Wo   = (const float*)d_in[13];
    const float* bo   = (const float*)d_in[14];
    const float* W_ip = (const float*)d_in[15];
    const float* b_ip = (const float*)d_in[16];
    const float* W_tp = (const float*)d_in[17];
    const float* b_tp = (const float*)d_in[18];
    const float* W_fp = (const float*)d_in[19];
    const float* b_fp = (const float*)d_in[20];
    const float* Wc1  = (const float*)d_in[21];
    const float* bc1  = (const float*)d_in[22];
    const float* Wc2  = (const float*)d_in[23];
    const float* bc2  = (const float*)d_in[24];
    float* out = (float*)d_out;

    const int B = in_sizes[0] / 512;

    setup_all<<<17, 256>>>(fq, Wq, bq, Wk, bk, bv, Wo, bo, W_fp, b_fp);
    setup_fuse<<<25, 256>>>(W_ip, W_tp, Wc1, b_ip, b_tp, bc1);
    setup_conv<<<1024, 256>>>(W_ie, W_te);
    setup_conv2<<<1104, 256>>>(Wv, Wc2);

    cudaFuncSetAttribute(enc_kernel, cudaFuncAttributeMaxDynamicSharedMemorySize,
                         ENC_SMEM);
    enc_kernel<<<dim3(B / 64, 2), 256, ENC_SMEM>>>(img, txt, b_ie, b_te);

    cudaFuncSetAttribute(tail_mma, cudaFuncAttributeMaxDynamicSharedMemorySize,
                         TAIL_SMEM);
    tail_mma<<<B / 32, 256, TAIL_SMEM>>>(bc1, bc2, out);
}

// round 16
// speedup vs baseline: 1.2897x; 1.0271x over previous
#include <cuda_runtime.h>
#include <cuda_bf16.h>
#include <math.h>

typedef unsigned long long u64;
typedef unsigned int u32;
typedef unsigned short u16;
typedef __nv_bfloat16 bf16;
#define BMAX 131072

#define MMA16816(c, a, b0_, b1_)                                              \
    asm volatile("mma.sync.aligned.m16n8k16.row.col.f32.bf16.bf16.f32 "       \
                 "{%0,%1,%2,%3},{%4,%5,%6,%7},{%8,%9},{%0,%1,%2,%3};"         \
                 : "+f"((c)[0]), "+f"((c)[1]), "+f"((c)[2]), "+f"((c)[3])     \
                 : "r"((a)[0]), "r"((a)[1]), "r"((a)[2]), "r"((a)[3]),        \
                   "r"(b0_), "r"(b1_))

__device__ __forceinline__ void splitf(float x, u16& h, u16& l) {
    bf16 hb = __float2bfloat16_rn(x);
    bf16 lb = __float2bfloat16_rn(x - __bfloat162float(hb));
    h = *(u16*)&hb; l = *(u16*)&lb;
}
__device__ __forceinline__ u32 packsplit(float x) {
    u16 h, l;
    splitf(x, h, l);
    return (u32)h | ((u32)l << 16);
}

// ------------------------------ device globals ------------------------------
__device__ float g_q[256];
__device__ float g_wk[4 * 256];
__device__ float g_ck[4];
__device__ float g_tmp[256];
__device__ float g_Wof[256 * 512];
__device__ float g_bof[512];
__device__ float g_W5c[3 * 256 * 256];   // [b][k][n]
__device__ float g_b5c[3 * 256];
__device__ u32   g_ep0[(size_t)BMAX * 256];  // enc_img split pair (hi | lo<<16)
__device__ u32   g_ep1[(size_t)BMAX * 256];  // enc_txt split pair
__device__ int   g_fi[BMAX], g_ft[BMAX];
__device__ u16   g_Wmh[2 * 256 * 512], g_Wml[2 * 256 * 512];   // enc W [mod][n][k]
__device__ u16   g_Wvh[256 * 256],     g_Wvl[256 * 256];       // Wv^T  [n][k]
__device__ u16   g_W5h[3 * 256 * 256], g_W5l[3 * 256 * 256];   // W5c^T [b][n][k]
__device__ u16   g_Wch[80 * 256],      g_Wcl[80 * 256];        // Wc2^T [n][k]

// ---------------------------- setup kernel 1 --------------------------------
// grid 33: block 0 = small precomputes; blocks 1..32 = Wof tiles (64x64,
// 4 it x 8 jt) for better SM coverage.
__global__ void setup_all(const float* __restrict__ fq, const float* __restrict__ Wq,
                          const float* __restrict__ bq, const float* __restrict__ Wk,
                          const float* __restrict__ bk, const float* __restrict__ bv,
                          const float* __restrict__ Wo, const float* __restrict__ bo,
                          const float* __restrict__ Wfp, const float* __restrict__ bfp) {
    __shared__ float sA[64 * 65];
    int t = threadIdx.x;
    if (blockIdx.x == 0) {
        {
            float s = bq[t];
#pragma unroll 8
            for (int k = 0; k < 256; k++) s = fmaf(fq[k], Wq[k * 256 + t], s);
            g_q[t] = s;
        }
        __syncthreads();
#pragma unroll
        for (int l = 0; l < 4; l++) {
            int idx = t + l * 256;
            int h = idx >> 8, j = idx & 255;
            float s = 0.f;
#pragma unroll 8
            for (int d = 0; d < 64; d++)
                s = fmaf(Wk[j * 256 + h * 64 + d], g_q[h * 64 + d], s);
            g_wk[h * 256 + j] = s;
        }
        if (t < 4) {
            float c = 0.f;
#pragma unroll 8
            for (int d = 0; d < 64; d++) c = fmaf(bk[t * 64 + d], g_q[t * 64 + d], c);
            g_ck[t] = c;
        }
        __syncthreads();
        {
            float s = bo[t];
#pragma unroll 8
            for (int k = 0; k < 256; k++) s = fmaf(bv[k], Wo[k * 256 + t], s);
            g_tmp[t] = s;
        }
        __syncthreads();
#pragma unroll
        for (int l = 0; l < 2; l++) {
            int j = t + l * 256;
            float s = bfp[j];
#pragma unroll 8
            for (int m = 0; m < 256; m++) s = fmaf(g_tmp[m], Wfp[m * 512 + j], s);
            g_bof[j] = s;
        }
        return;
    }
    int bid = blockIdx.x - 1;           // 0..31
    int tx = t & 31, ty = t >> 5;
    int it = bid >> 3, jt = bid & 7;    // 4 row tiles x 8 col tiles (64 cols)
    float acc[8][2];
#pragma unroll
    for (int i = 0; i < 8; i++) { acc[i][0] = 0.f; acc[i][1] = 0.f; }
    for (int mc = 0; mc < 256; mc += 64) {
        __syncthreads();
#pragma unroll
        for (int l = 0; l < 16; l++) {
            int idx = t + l * 256;
            int r = idx >> 6, k = idx & 63;
            sA[r * 65 + k] = Wo[(it * 64 + r) * 256 + mc + k];
        }
        __syncthreads();
#pragma unroll 2
        for (int k = 0; k < 64; k++) {
            const float* Wp = Wfp + (size_t)(mc + k) * 512 + jt * 64 + tx;
            float w0 = Wp[0], w1 = Wp[32];
#pragma unroll
            for (int i = 0; i < 8; i++) {
                float a = sA[(ty * 8 + i) * 65 + k];
                acc[i][0] = fmaf(a, w0, acc[i][0]);
                acc[i][1] = fmaf(a, w1, acc[i][1]);
            }
        }
    }
    __syncthreads();
#pragma unroll
    for (int i = 0; i < 8; i++) {
        g_Wof[(size_t)(it * 64 + ty * 8 + i) * 512 + jt * 64 + tx]      = acc[i][0];
        g_Wof[(size_t)(it * 64 + ty * 8 + i) * 512 + jt * 64 + tx + 32] = acc[i][1];
    }
}

// ---------------------------- setup kernel 2 --------------------------------
// grid 49: blocks 0..47 = W5c tiles (3 branches x 4 it x 4 jt, 64x64, K=512);
// block 48 = b5c.
__global__ void setup_fuse(const float* __restrict__ Wip, const float* __restrict__ Wtp,
                           const float* __restrict__ Wc1, const float* __restrict__ bip,
                           const float* __restrict__ btp, const float* __restrict__ bc1) {
    __shared__ float sA[64 * 65];
    int t = threadIdx.x;
    if (blockIdx.x == 48) {
#pragma unroll
        for (int b = 0; b < 3; b++) {
            const float* b5 = (b == 0) ? g_bof : (b == 1) ? bip : btp;
            float s = bc1[t];
#pragma unroll 8
            for (int m = 0; m < 512; m++) s = fmaf(b5[m], Wc1[m * 256 + t], s);
            g_b5c[b * 256 + t] = s;
        }
        return;
    }
    int b = blockIdx.x >> 4, bid = blockIdx.x & 15;
    int it = bid >> 2, jt = bid & 3;    // 4 row tiles x 4 col tiles (64 cols)
    const float* A = (b == 0) ? g_Wof : (b == 1) ? Wip : Wtp;
    int tx = t & 31, ty = t >> 5;
    float acc[8][2];
#pragma unroll
    for (int i = 0; i < 8; i++) { acc[i][0] = 0.f; acc[i][1] = 0.f; }
    for (int mc = 0; mc < 512; mc += 64) {
        __syncthreads();
#pragma unroll
        for (int l = 0; l < 16; l++) {
            int idx = t + l * 256;
            int r = idx >> 6, k = idx & 63;
            sA[r * 65 + k] = A[(size_t)(it * 64 + r) * 512 + mc + k];
        }
        __syncthreads();
#pragma unroll 2
        for (int m = 0; m < 64; m++) {
            const float* Wp = Wc1 + (size_t)(mc + m) * 256 + jt * 64 + tx;
            float w0 = Wp[0], w1 = Wp[32];
#pragma unroll
            for (int i = 0; i < 8; i++) {
                float a = sA[(ty * 8 + i) * 65 + m];
                acc[i][0] = fmaf(a, w0, acc[i][0]);
                acc[i][1] = fmaf(a, w1, acc[i][1]);
            }
        }
    }
    __syncthreads();
#pragma unroll
    for (int i = 0; i < 8; i++) {
        size_t o = (size_t)b * 65536 + (size_t)(it * 64 + ty * 8 + i) * 256 + jt * 64 + tx;
        g_W5c[o]      = acc[i][0];
        g_W5c[o + 32] = acc[i][1];
    }
}

// ---------------- setup 3/4: split-convert weights ----------------
__global__ void setup_conv(const float* __restrict__ Wie, const float* __restrict__ Wte) {
    int idx = blockIdx.x * 256 + threadIdx.x;
    int mod = idx >> 17, loc = idx & 131071;
    int n = loc >> 9, k = loc & 511;
    const float* W = mod ? Wte : Wie;
    u16 h, l;
    splitf(W[(size_t)k * 256 + n], h, l);
    size_t o = (size_t)mod * 131072 + (size_t)n * 512 + k;
    g_Wmh[o] = h; g_Wml[o] = l;
}
__global__ void setup_conv2(const float* __restrict__ Wv, const float* __restrict__ Wc2) {
    int idx = blockIdx.x * 256 + threadIdx.x;
    u16 h, l;
    if (idx < 65536) {
        int n = idx >> 8, k = idx & 255;
        splitf(Wv[k * 256 + n], h, l);
        g_Wvh[n * 256 + k] = h; g_Wvl[n * 256 + k] = l;
    } else if (idx < 262144) {
        int t = idx - 65536, b = t >> 16, r = t & 65535;
        int n = r >> 8, k = r & 255;
        splitf(g_W5c[b * 65536 + k * 256 + n], h, l);
        g_W5h[b * 65536 + n * 256 + k] = h; g_W5l[b * 65536 + n * 256 + k] = l;
    } else if (idx < 282624) {
        int t = idx - 262144, n = t >> 8, k = t & 255;
        splitf(Wc2[k * 80 + n], h, l);
        g_Wch[n * 256 + k] = h; g_Wcl[n * 256 + k] = l;
    }
}

// -------- encoder kernel (HMMA) + flags + packed split-plane output --------
#define ENC_STRIDE 264
#define ENC_SQ (2 * 64 * ENC_STRIDE)          // u16 offset of sq scratch
#define ENC_SMEM (2 * 64 * ENC_STRIDE * 2 + 64 * 64 * 4)

__global__ void __launch_bounds__(256, 2)
enc_kernel(const float* __restrict__ img, const float* __restrict__ txt,
           const float* __restrict__ b_ie, const float* __restrict__ b_te) {
    extern __shared__ u16 smh[];
    u16* Ah = smh;
    u16* Al = smh + 64 * ENC_STRIDE;
    float* sq = (float*)(smh + ENC_SQ);       // [64][64]
    const int tid = threadIdx.x;
    const int lane = tid & 31, w = tid >> 5;
    const int g = lane >> 2, tig = lane & 3;
    const int mod = blockIdx.y;
    const size_t row0 = (size_t)blockIdx.x * 64;
    const float* X  = mod ? txt : img;
    const float* bb = mod ? b_te : b_ie;
    const u16* Wh = g_Wmh + (size_t)mod * 131072;
    const u16* Wl = g_Wml + (size_t)mod * 131072;
    u32* eP = mod ? g_ep1 : g_ep0;
    int* fP = mod ? g_ft : g_fi;
    float acc[2][8][4] = {};

    for (int kc = 0; kc < 512; kc += 256) {
        __syncthreads();
#pragma unroll
        for (int l = 0; l < 16; l++) {
            int idx = tid + l * 256;
            int r = idx >> 6, k4 = idx & 63;
            float4 v = *(const float4*)(X + (row0 + r) * 512 + kc + k4 * 4);
            float ss = v.x * v.x + v.y * v.y + v.z * v.z + v.w * v.w;
            if (kc == 0) sq[r * 64 + k4] = ss;
            else         sq[r * 64 + k4] += ss;
            u16 h[4], lo[4];
            splitf(v.x, h[0], lo[0]); splitf(v.y, h[1], lo[1]);
            splitf(v.z, h[2], lo[2]); splitf(v.w, h[3], lo[3]);
            u32 base = r * ENC_STRIDE + k4 * 4;
            *(u32*)(Ah + base)     = (u32)h[0] | ((u32)h[1] << 16);
            *(u32*)(Ah + base + 2) = (u32)h[2] | ((u32)h[3] << 16);
            *(u32*)(Al + base)     = (u32)lo[0] | ((u32)lo[1] << 16);
            *(u32*)(Al + base + 2) = (u32)lo[2] | ((u32)lo[3] << 16);
        }
        __syncthreads();
#pragma unroll 2
        for (int ks = 0; ks < 16; ks++) {
            int kof = kc + ks * 16;
            u32 ah[2][4], al[2][4];
#pragma unroll
            for (int mt = 0; mt < 2; mt++) {
                int m = w * 32 + mt * 16 + g;
                size_t o0 = (size_t)m * 512 + kof + 2 * tig, o8 = o0 + 8 * 512;
                ah[mt][0] = *(const u32*)(Wh + o0); ah[mt][1] = *(const u32*)(Wh + o8);
                ah[mt][2] = *(const u32*)(Wh + o0 + 8); ah[mt][3] = *(const u32*)(Wh + o8 + 8);
                al[mt][0] = *(const u32*)(Wl + o0); al[mt][1] = *(const u32*)(Wl + o8);
                al[mt][2] = *(const u32*)(Wl + o0 + 8); al[mt][3] = *(const u32*)(Wl + o8 + 8);
            }
            int ko = ks * 16;
#pragma unroll
            for (int nt = 0; nt < 8; nt++) {
                const u16* ar  = Ah + (nt * 8 + g) * ENC_STRIDE + ko;
                const u16* arl = Al + (nt * 8 + g) * ENC_STRIDE + ko;
                u32 bh0 = *(const u32*)(ar + 2 * tig);
                u32 bh1 = *(const u32*)(ar + 2 * tig + 8);
                u32 bl0 = *(const u32*)(arl + 2 * tig);
                u32 bl1 = *(const u32*)(arl + 2 * tig + 8);
#pragma unroll
                for (int mt = 0; mt < 2; mt++) {
                    MMA16816(acc[mt][nt], ah[mt], bh0, bh1);
                    MMA16816(acc[mt][nt], ah[mt], bl0, bl1);
                    MMA16816(acc[mt][nt], al[mt], bh0, bh1);
                }
            }
        }
    }
    // flags (sq complete after last staging sync)
    if (tid < 64) {
        float s = 0.f;
#pragma unroll 8
        for (int i = 0; i < 64; i++) s += sq[tid * 64 + i];
        fP[row0 + tid] = (s > 1e-12f) ? 1 : 0;
    }
    // epilogue: bias + relu -> packed split plane
#pragma unroll
    for (int mt = 0; mt < 2; mt++) {
        int m0 = w * 32 + mt * 16 + g;
        float b0 = bb[m0], b8 = bb[m0 + 8];
#pragma unroll
        for (int nt = 0; nt < 8; nt++) {
            size_t r0 = row0 + nt * 8 + 2 * tig;
            float v;
            v = acc[mt][nt][0] + b0; eP[r0 * 256 + m0]           = packsplit(v > 0.f ? v : 0.f);
            v = acc[mt][nt][1] + b0; eP[(r0 + 1) * 256 + m0]     = packsplit(v > 0.f ? v : 0.f);
            v = acc[mt][nt][2] + b8; eP[r0 * 256 + m0 + 8]       = packsplit(v > 0.f ? v : 0.f);
            v = acc[mt][nt][3] + b8; eP[(r0 + 1) * 256 + m0 + 8] = packsplit(v > 0.f ? v : 0.f);
        }
    }
}

// --------------------------- tail kernel (HMMA) -----------------------------
// 32 rows/CTA (sorted), 256 threads, 2 CTAs/SM. Split-bf16 smem planes.
#define SR 264
#define T_E0H 0
#define T_E0L 8448
#define T_E1H 16896
#define T_E1L 25344
#define T_XSH 33792
#define T_XSL 42240
#define T_FLT 50688
#define TAIL_SMEM 102400

__global__ void __launch_bounds__(256, 2)
tail_mma(const float* __restrict__ bc1, const float* __restrict__ bc2,
         float* __restrict__ out) {
    extern __shared__ u16 sh[];
    u16* E0H = sh + T_E0H; u16* E0L = sh + T_E0L;
    u16* E1H = sh + T_E1H; u16* E1L = sh + T_E1L;
    u16* XSH = sh + T_XSH; u16* XSL = sh + T_XSL;
    float* sattn = (float*)(sh + T_FLT);
    int* sflag = (int*)(sattn + 128);
    int* sperm = sflag + 32;
    int* ssbr  = sperm + 32;
    int* snb   = ssbr + 32;
    float* scratch = (float*)(sh + T_XSH);  // overlays xs (dead until GEMM1 epi)

    const int tid = threadIdx.x, lane = tid & 31, w = tid >> 5;
    const int g = lane >> 2, tig = lane & 3;
    const size_t row0 = (size_t)blockIdx.x * 32;

    // P0: flags (from enc) + sort
    if (tid < 32) {
        int fi = g_fi[row0 + tid], ft = g_ft[row0 + tid];
        sflag[tid] = (fi && ft) ? 1 : (fi ? 2 : (ft ? 3 : 0));
    }
    __syncthreads();
    if (tid == 0) {
        int cnt[4] = {0, 0, 0, 0};
        for (int r = 0; r < 32; r++) cnt[sflag[r]]++;
        int base[4];
        base[1] = 0; base[2] = cnt[1]; base[3] = cnt[1] + cnt[2]; base[0] = base[3] + cnt[3];
        for (int r = 0; r < 32; r++) {
            int f = sflag[r], s = base[f]++;
            sperm[s] = r; ssbr[s] = f;
        }
        *snb = cnt[1];
    }
    __syncthreads();

    // P1: unpack packed split planes (sorted) + per-head dot partials
    {
        int s = tid >> 3, p = tid & 7;
        size_t gr = row0 + sperm[s];
        int k0 = p * 32;
        float d[2][4] = {};
#pragma unroll
        for (int m2 = 0; m2 < 2; m2++) {
            const u32* src = (m2 ? g_ep1 : g_ep0) + gr * 256 + k0;
            u16* PH = m2 ? E1H : E0H;
            u16* PL = m2 ? E1L : E0L;
#pragma unroll
            for (int q = 0; q < 8; q++) {
                uint4 v = *(const uint4*)(src + q * 4);
                int k = k0 + q * 4;
                *(u32*)(PH + s * SR + k)     = (v.x & 0xffffu) | ((v.y & 0xffffu) << 16);
                *(u32*)(PH + s * SR + k + 2) = (v.z & 0xffffu) | ((v.w & 0xffffu) << 16);
                *(u32*)(PL + s * SR + k)     = (v.x >> 16) | (v.y & 0xffff0000u);
                *(u32*)(PL + s * SR + k + 2) = (v.z >> 16) | (v.w & 0xffff0000u);
                float e0 = __uint_as_float(v.x << 16) + __uint_as_float(v.x & 0xffff0000u);
                float e1 = __uint_as_float(v.y << 16) + __uint_as_float(v.y & 0xffff0000u);
                float e2 = __uint_as_float(v.z << 16) + __uint_as_float(v.z & 0xffff0000u);
                float e3 = __uint_as_float(v.w << 16) + __uint_as_float(v.w & 0xffff0000u);
#pragma unroll
                for (int h = 0; h < 4; h++) {
                    const float* wk = g_wk + h * 256 + k;
                    d[m2][h] = fmaf(e0, wk[0], d[m2][h]);
                    d[m2][h] = fmaf(e1, wk[1], d[m2][h]);
                    d[m2][h] = fmaf(e2, wk[2], d[m2][h]);
                    d[m2][h] = fmaf(e3, wk[3], d[m2][h]);
                }
            }
        }
#pragma unroll
        for (int h = 0; h < 4; h++) {
            scratch[(s * 8 + p) * 4 + h] = d[0][h];
            scratch[1024 + (s * 8 + p) * 4 + h] = d[1][h];
        }
    }
    __syncthreads();
    if (tid < 128) {
        int s = tid >> 2, h = tid & 3;
        float d0 = 0.f, d1 = 0.f;
#pragma unroll
        for (int p = 0; p < 8; p++) {
            d0 += scratch[(s * 8 + p) * 4 + h];
            d1 += scratch[1024 + (s * 8 + p) * 4 + h];
        }
        float s0 = (d0 + g_ck[h]) * 0.125f, s1 = (d1 + g_ck[h]) * 0.125f;
        float m = fmaxf(s0, s1);
        float e0 = expf(s0 - m), e1 = expf(s1 - m);
        sattn[s * 4 + h] = e0 / (e0 + e1);
    }
    __syncthreads();
    const int nb = *snb;

    // GEMM1: q0=e0@Wv, q1=e1@Wv (mt outer); lerp epilogue -> xs
    if (nb > 0) {
        int h = w >> 1, cw = w * 32;
#pragma unroll
        for (int mt = 0; mt < 2; mt++) {
            float q0a[4][4] = {}, q1a[4][4] = {};
            const int m = cw + mt * 16 + g;
#pragma unroll 2
            for (int ks = 0; ks < 16; ks++) {
                size_t o = (size_t)m * 256 + ks * 16 + 2 * tig, o8 = o + 2048;
                u32 ah[4] = {*(const u32*)(g_Wvh + o), *(const u32*)(g_Wvh + o8),
                             *(const u32*)(g_Wvh + o + 8), *(const u32*)(g_Wvh + o8 + 8)};
                u32 al[4] = {*(const u32*)(g_Wvl + o), *(const u32*)(g_Wvl + o8),
                             *(const u32*)(g_Wvl + o + 8), *(const u32*)(g_Wvl + o8 + 8)};
#pragma unroll
                for (int nt = 0; nt < 4; nt++) {
                    if (nt * 8 < nb) {
                        int base = (nt * 8 + g) * SR + ks * 16 + 2 * tig;
                        u32 x0h0 = *(const u32*)(E0H + base), x0h1 = *(const u32*)(E0H + base + 8);
                        u32 x0l0 = *(const u32*)(E0L + base), x0l1 = *(const u32*)(E0L + base + 8);
                        u32 x1h0 = *(const u32*)(E1H + base), x1h1 = *(const u32*)(E1H + base + 8);
                        u32 x1l0 = *(const u32*)(E1L + base), x1l1 = *(const u32*)(E1L + base + 8);
                        MMA16816(q0a[nt], ah, x0h0, x0h1);
                        MMA16816(q0a[nt], ah, x0l0, x0l1);
                        MMA16816(q0a[nt], al, x0h0, x0h1);
                        MMA16816(q1a[nt], ah, x1h0, x1h1);
                        MMA16816(q1a[nt], ah, x1l0, x1l1);
                        MMA16816(q1a[nt], al, x1h0, x1h1);
                    }
                }
            }
#pragma unroll
            for (int nt = 0; nt < 4; nt++) {
                if (nt * 8 < nb) {
                    int r0 = nt * 8 + 2 * tig;
#pragma unroll
                    for (int pr = 0; pr < 2; pr++) {
                        int r = r0 + pr;
                        if (r < nb) {
                            float a0 = sattn[r * 4 + h];
                            float v0 = fmaf(a0, q0a[nt][pr] - q1a[nt][pr], q1a[nt][pr]);
                            float v8 = fmaf(a0, q0a[nt][2 + pr] - q1a[nt][2 + pr],
                                            q1a[nt][2 + pr]);
                            u16 hh, ll;
                            splitf(v0, hh, ll); XSH[r * SR + m] = hh;     XSL[r * SR + m] = ll;
                            splitf(v8, hh, ll); XSH[r * SR + m + 8] = hh; XSL[r * SR + m + 8] = ll;
                        }
                    }
                }
            }
        }
    }
    __syncthreads();

    // P4: xs for non-both rows (copy e0/e1 or zero)
    for (int idx = tid; idx < 32 * 8; idx += 256) {
        int s = idx >> 3, q = idx & 7;
        if (s < nb) continue;
        int f = ssbr[s];
        uint4 z = make_uint4(0, 0, 0, 0);
#pragma unroll
        for (int j = 0; j < 4; j++) {
            uint4 vh = z, vl = z;
            if (f == 2) {
                vh = ((const uint4*)(E0H + s * SR))[q * 4 + j];
                vl = ((const uint4*)(E0L + s * SR))[q * 4 + j];
            } else if (f == 3) {
                vh = ((const uint4*)(E1H + s * SR))[q * 4 + j];
                vl = ((const uint4*)(E1L + s * SR))[q * 4 + j];
            }
            ((uint4*)(XSH + s * SR))[q * 4 + j] = vh;
            ((uint4*)(XSL + s * SR))[q * 4 + j] = vl;
        }
    }
    __syncthreads();

    // GEMM2: h1 = relu(xs @ W5c[branch] + bias) -> overlay e0 planes
    {
        int cw = w * 32;
        float a2[2][4][4] = {};
        for (int seg = 1; seg <= 3; seg++) {
            u32 ntm = 0;
            for (int i = 0; i < 32; i++)
                if (ssbr[i] == seg) ntm |= 1u << (i >> 3);
            if (!ntm) continue;
            const u16* WH = g_W5h + (size_t)(seg - 1) * 65536;
            const u16* WL = g_W5l + (size_t)(seg - 1) * 65536;
#pragma unroll 2
            for (int ks = 0; ks < 16; ks++) {
                u32 ah[2][4], al[2][4];
#pragma unroll
                for (int mt = 0; mt < 2; mt++) {
                    int m = cw + mt * 16 + g;
                    size_t o = (size_t)m * 256 + ks * 16 + 2 * tig, o8 = o + 2048;
                    ah[mt][0] = *(const u32*)(WH + o); ah[mt][1] = *(const u32*)(WH + o8);
                    ah[mt][2] = *(const u32*)(WH + o + 8); ah[mt][3] = *(const u32*)(WH + o8 + 8);
                    al[mt][0] = *(const u32*)(WL + o); al[mt][1] = *(const u32*)(WL + o8);
                    al[mt][2] = *(const u32*)(WL + o + 8); al[mt][3] = *(const u32*)(WL + o8 + 8);
                }
#pragma unroll
                for (int nt = 0; nt < 4; nt++) {
                    if (!((ntm >> nt) & 1)) continue;
                    int s = nt * 8 + g;
                    bool on = (ssbr[s] == seg);
                    int base = s * SR + ks * 16 + 2 * tig;
                    u32 bh0 = 0, bh1 = 0, bl0 = 0, bl1 = 0;
                    if (on) {
                        bh0 = *(const u32*)(XSH + base); bh1 = *(const u32*)(XSH + base + 8);
                        bl0 = *(const u32*)(XSL + base); bl1 = *(const u32*)(XSL + base + 8);
                    }
#pragma unroll
                    for (int mt = 0; mt < 2; mt++) {
                        MMA16816(a2[mt][nt], ah[mt], bh0, bh1);
                        MMA16816(a2[mt][nt], ah[mt], bl0, bl1);
                        MMA16816(a2[mt][nt], al[mt], bh0, bh1);
                    }
                }
            }
        }
#pragma unroll
        for (int nt = 0; nt < 4; nt++)
#pragma unroll
            for (int mt = 0; mt < 2; mt++) {
                int r0 = nt * 8 + 2 * tig, m0 = cw + mt * 16 + g;
#pragma unroll
                for (int pr = 0; pr < 2; pr++) {
                    int r = r0 + pr;
                    int f = ssbr[r];
                    float b0 = f ? g_b5c[(f - 1) * 256 + m0] : bc1[m0];
                    float b8 = f ? g_b5c[(f - 1) * 256 + m0 + 8] : bc1[m0 + 8];
                    float v0 = a2[mt][nt][pr] + b0;     v0 = v0 > 0.f ? v0 : 0.f;
                    float v8 = a2[mt][nt][2 + pr] + b8; v8 = v8 > 0.f ? v8 : 0.f;
                    u16 hh, ll;
                    splitf(v0, hh, ll); E0H[r * SR + m0] = hh;     E0L[r * SR + m0] = ll;
                    splitf(v8, hh, ll); E0H[r * SR + m0 + 8] = hh; E0L[r * SR + m0 + 8] = ll;
                }
            }
    }
    __syncthreads();

    // GEMM3: out = h1 @ Wc2 + bc2 (warps 0..4, 16 cols each)
    if (w < 5) {
        float a3[4][4] = {};
#pragma unroll 2
        for (int ks = 0; ks < 16; ks++) {
            int m = w * 16 + g;
            size_t o = (size_t)m * 256 + ks * 16 + 2 * tig, o8 = o + 2048;
            u32 ah[4] = {*(const u32*)(g_Wch + o), *(const u32*)(g_Wch + o8),
                         *(const u32*)(g_Wch + o + 8), *(const u32*)(g_Wch + o8 + 8)};
            u32 al[4] = {*(const u32*)(g_Wcl + o), *(const u32*)(g_Wcl + o8),
                         *(const u32*)(g_Wcl + o + 8), *(const u32*)(g_Wcl + o8 + 8)};
#pragma unroll
            for (int nt = 0; nt < 4; nt++) {
                int base = (nt * 8 + g) * SR + ks * 16 + 2 * tig;
                u32 bh0 = *(const u32*)(E0H + base), bh1 = *(const u32*)(E0H + base + 8);
                u32 bl0 = *(const u32*)(E0L + base), bl1 = *(const u32*)(E0L + base + 8);
                MMA16816(a3[nt], ah, bh0, bh1);
                MMA16816(a3[nt], ah, bl0, bl1);
                MMA16816(a3[nt], al, bh0, bh1);
            }
        }
#pragma unroll
        for (int nt = 0; nt < 4; nt++) {
            int r0 = nt * 8 + 2 * tig, m0 = w * 16 + g;
#pragma unroll
            for (int pr = 0; pr < 2; pr++) {
                size_t ro = (row0 + sperm[r0 + pr]) * 80;
                out[ro + m0]     = a3[nt][pr] + bc2[m0];
                out[ro + m0 + 8] = a3[nt][2 + pr] + bc2[m0 + 8];
            }
        }
    }
}

// ------------------------------- launch ------------------------------------
extern "C" void kernel_launch(void* const* d_in, const int* in_sizes, int n_in,
                              void* d_out, int out_size) {
    const float* img  = (const float*)d_in[0];
    const float* txt  = (const float*)d_in[1];
    const float* W_ie = (const float*)d_in[2];
    const float* b_ie = (const float*)d_in[3];
    const float* W_te = (const float*)d_in[4];
    const float* b_te = (const float*)d_in[5];
    const float* fq   = (const float*)d_in[6];
    const float* Wq   = (const float*)d_in[7];
    const float* bq   = (const float*)d_in[8];
    const float* Wk   = (const float*)d_in[9];
    const float* bk   = (const float*)d_in[10];
    const float* Wv   = (const float*)d_in[11];
    const float* bv   = (const float*)d_in[12];
    const float* Wo   = (const float*)d_in[13];
    const float* bo   = (const float*)d_in[14];
    const float* W_ip = (const float*)d_in[15];
    const float* b_ip = (const float*)d_in[16];
    const float* W_tp = (const float*)d_in[17];
    const float* b_tp = (const float*)d_in[18];
    const float* W_fp = (const float*)d_in[19];
    const float* b_fp = (const float*)d_in[20];
    const float* Wc1  = (const float*)d_in[21];
    const float* bc1  = (const float*)d_in[22];
    const float* Wc2  = (const float*)d_in[23];
    const float* bc2  = (const float*)d_in[24];
    float* out = (float*)d_out;

    const int B = in_sizes[0] / 512;

    setup_all<<<33, 256>>>(fq, Wq, bq, Wk, bk, bv, Wo, bo, W_fp, b_fp);
    setup_fuse<<<49, 256>>>(W_ip, W_tp, Wc1, b_ip, b_tp, bc1);
    setup_conv<<<1024, 256>>>(W_ie, W_te);
    setup_conv2<<<1104, 256>>>(Wv, Wc2);

    cudaFuncSetAttribute(enc_kernel, cudaFuncAttributeMaxDynamicSharedMemorySize,
                         ENC_SMEM);
    enc_kernel<<<dim3(B / 64, 2), 256, ENC_SMEM>>>(img, txt, b_ie, b_te);

    cudaFuncSetAttribute(tail_mma, cudaFuncAttributeMaxDynamicSharedMemorySize,
                         TAIL_SMEM);
    tail_mma<<<B / 32, 256, TAIL_SMEM>>>(bc1, bc2, out);
}

// round 17
// speedup vs baseline: 1.4533x; 1.1268x over previous
#include <cuda_runtime.h>
#include <cuda_bf16.h>
#include <math.h>

typedef unsigned long long u64;
typedef unsigned int u32;
typedef unsigned short u16;
typedef __nv_bfloat16 bf16;
#define BMAX 131072

#define MMA16816(c, a, b0_, b1_)                                              \
    asm volatile("mma.sync.aligned.m16n8k16.row.col.f32.bf16.bf16.f32 "       \
                 "{%0,%1,%2,%3},{%4,%5,%6,%7},{%8,%9},{%0,%1,%2,%3};"         \
                 : "+f"((c)[0]), "+f"((c)[1]), "+f"((c)[2]), "+f"((c)[3])     \
                 : "r"((a)[0]), "r"((a)[1]), "r"((a)[2]), "r"((a)[3]),        \
                   "r"(b0_), "r"(b1_))

__device__ __forceinline__ void splitf(float x, u16& h, u16& l) {
    bf16 hb = __float2bfloat16_rn(x);
    bf16 lb = __float2bfloat16_rn(x - __bfloat162float(hb));
    h = *(u16*)&hb; l = *(u16*)&lb;
}
__device__ __forceinline__ u32 packsplit(float x) {
    u16 h, l;
    splitf(x, h, l);
    return (u32)h | ((u32)l << 16);
}

// ------------------------------ device globals ------------------------------
__device__ float g_q[256];
__device__ float g_wk[4 * 256];
__device__ float g_ck[4];
__device__ float g_tmp[256];
__device__ float g_Wof[256 * 512];
__device__ float g_bof[512];
__device__ float g_W5c[3 * 256 * 256];   // [b][k][n]
__device__ float g_b5c[3 * 256];
__device__ u32   g_ep0[(size_t)BMAX * 256];  // enc_img split pair (hi | lo<<16)
__device__ u32   g_ep1[(size_t)BMAX * 256];  // enc_txt split pair
__device__ int   g_fi[BMAX], g_ft[BMAX];
__device__ u16   g_Wmh[2 * 256 * 512], g_Wml[2 * 256 * 512];   // enc W [mod][n][k]
__device__ u16   g_Wvh[256 * 256],     g_Wvl[256 * 256];       // Wv^T  [n][k]
__device__ u16   g_W5h[3 * 256 * 256], g_W5l[3 * 256 * 256];   // W5c^T [b][n][k]
__device__ u16   g_Wch[80 * 256],      g_Wcl[80 * 256];        // Wc2^T [n][k]

// ---------------------------- setup kernel 1 --------------------------------
__global__ void setup_all(const float* __restrict__ fq, const float* __restrict__ Wq,
                          const float* __restrict__ bq, const float* __restrict__ Wk,
                          const float* __restrict__ bk, const float* __restrict__ bv,
                          const float* __restrict__ Wo, const float* __restrict__ bo,
                          const float* __restrict__ Wfp, const float* __restrict__ bfp) {
    __shared__ float sA[64 * 65];
    int t = threadIdx.x;
    if (blockIdx.x == 0) {
        {
            float s = bq[t];
#pragma unroll 8
            for (int k = 0; k < 256; k++) s = fmaf(fq[k], Wq[k * 256 + t], s);
            g_q[t] = s;
        }
        __syncthreads();
#pragma unroll
        for (int l = 0; l < 4; l++) {
            int idx = t + l * 256;
            int h = idx >> 8, j = idx & 255;
            float s = 0.f;
#pragma unroll 8
            for (int d = 0; d < 64; d++)
                s = fmaf(Wk[j * 256 + h * 64 + d], g_q[h * 64 + d], s);
            g_wk[h * 256 + j] = s;
        }
        if (t < 4) {
            float c = 0.f;
#pragma unroll 8
            for (int d = 0; d < 64; d++) c = fmaf(bk[t * 64 + d], g_q[t * 64 + d], c);
            g_ck[t] = c;
        }
        __syncthreads();
        {
            float s = bo[t];
#pragma unroll 8
            for (int k = 0; k < 256; k++) s = fmaf(bv[k], Wo[k * 256 + t], s);
            g_tmp[t] = s;
        }
        __syncthreads();
#pragma unroll
        for (int l = 0; l < 2; l++) {
            int j = t + l * 256;
            float s = bfp[j];
#pragma unroll 8
            for (int m = 0; m < 256; m++) s = fmaf(g_tmp[m], Wfp[m * 512 + j], s);
            g_bof[j] = s;
        }
        return;
    }
    int bid = blockIdx.x - 1;           // 0..31
    int tx = t & 31, ty = t >> 5;
    int it = bid >> 3, jt = bid & 7;    // 4 row tiles x 8 col tiles (64 cols)
    float acc[8][2];
#pragma unroll
    for (int i = 0; i < 8; i++) { acc[i][0] = 0.f; acc[i][1] = 0.f; }
    for (int mc = 0; mc < 256; mc += 64) {
        __syncthreads();
#pragma unroll
        for (int l = 0; l < 16; l++) {
            int idx = t + l * 256;
            int r = idx >> 6, k = idx & 63;
            sA[r * 65 + k] = Wo[(it * 64 + r) * 256 + mc + k];
        }
        __syncthreads();
#pragma unroll 2
        for (int k = 0; k < 64; k++) {
            const float* Wp = Wfp + (size_t)(mc + k) * 512 + jt * 64 + tx;
            float w0 = Wp[0], w1 = Wp[32];
#pragma unroll
            for (int i = 0; i < 8; i++) {
                float a = sA[(ty * 8 + i) * 65 + k];
                acc[i][0] = fmaf(a, w0, acc[i][0]);
                acc[i][1] = fmaf(a, w1, acc[i][1]);
            }
        }
    }
    __syncthreads();
#pragma unroll
    for (int i = 0; i < 8; i++) {
        g_Wof[(size_t)(it * 64 + ty * 8 + i) * 512 + jt * 64 + tx]      = acc[i][0];
        g_Wof[(size_t)(it * 64 + ty * 8 + i) * 512 + jt * 64 + tx + 32] = acc[i][1];
    }
}

// ---------------------------- setup kernel 2 --------------------------------
__global__ void setup_fuse(const float* __restrict__ Wip, const float* __restrict__ Wtp,
                           const float* __restrict__ Wc1, const float* __restrict__ bip,
                           const float* __restrict__ btp, const float* __restrict__ bc1) {
    __shared__ float sA[64 * 65];
    int t = threadIdx.x;
    if (blockIdx.x == 48) {
#pragma unroll
        for (int b = 0; b < 3; b++) {
            const float* b5 = (b == 0) ? g_bof : (b == 1) ? bip : btp;
            float s = bc1[t];
#pragma unroll 8
            for (int m = 0; m < 512; m++) s = fmaf(b5[m], Wc1[m * 256 + t], s);
            g_b5c[b * 256 + t] = s;
        }
        return;
    }
    int b = blockIdx.x >> 4, bid = blockIdx.x & 15;
    int it = bid >> 2, jt = bid & 3;
    const float* A = (b == 0) ? g_Wof : (b == 1) ? Wip : Wtp;
    int tx = t & 31, ty = t >> 5;
    float acc[8][2];
#pragma unroll
    for (int i = 0; i < 8; i++) { acc[i][0] = 0.f; acc[i][1] = 0.f; }
    for (int mc = 0; mc < 512; mc += 64) {
        __syncthreads();
#pragma unroll
        for (int l = 0; l < 16; l++) {
            int idx = t + l * 256;
            int r = idx >> 6, k = idx & 63;
            sA[r * 65 + k] = A[(size_t)(it * 64 + r) * 512 + mc + k];
        }
        __syncthreads();
#pragma unroll 2
        for (int m = 0; m < 64; m++) {
            const float* Wp = Wc1 + (size_t)(mc + m) * 256 + jt * 64 + tx;
            float w0 = Wp[0], w1 = Wp[32];
#pragma unroll
            for (int i = 0; i < 8; i++) {
                float a = sA[(ty * 8 + i) * 65 + m];
                acc[i][0] = fmaf(a, w0, acc[i][0]);
                acc[i][1] = fmaf(a, w1, acc[i][1]);
            }
        }
    }
    __syncthreads();
#pragma unroll
    for (int i = 0; i < 8; i++) {
        size_t o = (size_t)b * 65536 + (size_t)(it * 64 + ty * 8 + i) * 256 + jt * 64 + tx;
        g_W5c[o]      = acc[i][0];
        g_W5c[o + 32] = acc[i][1];
    }
}

// ---------------- setup 3/4: split-convert weights ----------------
__global__ void setup_conv(const float* __restrict__ Wie, const float* __restrict__ Wte) {
    int idx = blockIdx.x * 256 + threadIdx.x;
    int mod = idx >> 17, loc = idx & 131071;
    int n = loc >> 9, k = loc & 511;
    const float* W = mod ? Wte : Wie;
    u16 h, l;
    splitf(W[(size_t)k * 256 + n], h, l);
    size_t o = (size_t)mod * 131072 + (size_t)n * 512 + k;
    g_Wmh[o] = h; g_Wml[o] = l;
}
__global__ void setup_conv2(const float* __restrict__ Wv, const float* __restrict__ Wc2) {
    int idx = blockIdx.x * 256 + threadIdx.x;
    u16 h, l;
    if (idx < 65536) {
        int n = idx >> 8, k = idx & 255;
        splitf(Wv[k * 256 + n], h, l);
        g_Wvh[n * 256 + k] = h; g_Wvl[n * 256 + k] = l;
    } else if (idx < 262144) {
        int t = idx - 65536, b = t >> 16, r = t & 65535;
        int n = r >> 8, k = r & 255;
        splitf(g_W5c[b * 65536 + k * 256 + n], h, l);
        g_W5h[b * 65536 + n * 256 + k] = h; g_W5l[b * 65536 + n * 256 + k] = l;
    } else if (idx < 282624) {
        int t = idx - 262144, n = t >> 8, k = t & 255;
        splitf(Wc2[k * 80 + n], h, l);
        g_Wch[n * 256 + k] = h; g_Wcl[n * 256 + k] = l;
    }
}

// -------- encoder kernel (HMMA) + flags + packed split-plane output --------
#define ENC_STRIDE 264
#define ENC_SQ (2 * 64 * ENC_STRIDE)
#define ENC_SMEM (2 * 64 * ENC_STRIDE * 2 + 64 * 64 * 4)

__global__ void __launch_bounds__(256, 2)
enc_kernel(const float* __restrict__ img, const float* __restrict__ txt,
           const float* __restrict__ b_ie, const float* __restrict__ b_te) {
    extern __shared__ u16 smh[];
    u16* Ah = smh;
    u16* Al = smh + 64 * ENC_STRIDE;
    float* sq = (float*)(smh + ENC_SQ);
    const int tid = threadIdx.x;
    const int lane = tid & 31, w = tid >> 5;
    const int g = lane >> 2, tig = lane & 3;
    const int mod = blockIdx.y;
    const size_t row0 = (size_t)blockIdx.x * 64;
    const float* X  = mod ? txt : img;
    const float* bb = mod ? b_te : b_ie;
    const u16* Wh = g_Wmh + (size_t)mod * 131072;
    const u16* Wl = g_Wml + (size_t)mod * 131072;
    u32* eP = mod ? g_ep1 : g_ep0;
    int* fP = mod ? g_ft : g_fi;
    float acc[2][8][4] = {};

    for (int kc = 0; kc < 512; kc += 256) {
        __syncthreads();
#pragma unroll
        for (int l = 0; l < 16; l++) {
            int idx = tid + l * 256;
            int r = idx >> 6, k4 = idx & 63;
            float4 v = *(const float4*)(X + (row0 + r) * 512 + kc + k4 * 4);
            float ss = v.x * v.x + v.y * v.y + v.z * v.z + v.w * v.w;
            if (kc == 0) sq[r * 64 + k4] = ss;
            else         sq[r * 64 + k4] += ss;
            u16 h[4], lo[4];
            splitf(v.x, h[0], lo[0]); splitf(v.y, h[1], lo[1]);
            splitf(v.z, h[2], lo[2]); splitf(v.w, h[3], lo[3]);
            u32 base = r * ENC_STRIDE + k4 * 4;
            *(u32*)(Ah + base)     = (u32)h[0] | ((u32)h[1] << 16);
            *(u32*)(Ah + base + 2) = (u32)h[2] | ((u32)h[3] << 16);
            *(u32*)(Al + base)     = (u32)lo[0] | ((u32)lo[1] << 16);
            *(u32*)(Al + base + 2) = (u32)lo[2] | ((u32)lo[3] << 16);
        }
        __syncthreads();
#pragma unroll 2
        for (int ks = 0; ks < 16; ks++) {
            int kof = kc + ks * 16;
            u32 ah[2][4], al[2][4];
#pragma unroll
            for (int mt = 0; mt < 2; mt++) {
                int m = w * 32 + mt * 16 + g;
                size_t o0 = (size_t)m * 512 + kof + 2 * tig, o8 = o0 + 8 * 512;
                ah[mt][0] = *(const u32*)(Wh + o0); ah[mt][1] = *(const u32*)(Wh + o8);
                ah[mt][2] = *(const u32*)(Wh + o0 + 8); ah[mt][3] = *(const u32*)(Wh + o8 + 8);
                al[mt][0] = *(const u32*)(Wl + o0); al[mt][1] = *(const u32*)(Wl + o8);
                al[mt][2] = *(const u32*)(Wl + o0 + 8); al[mt][3] = *(const u32*)(Wl + o8 + 8);
            }
            int ko = ks * 16;
#pragma unroll
            for (int nt = 0; nt < 8; nt++) {
                const u16* ar  = Ah + (nt * 8 + g) * ENC_STRIDE + ko;
                const u16* arl = Al + (nt * 8 + g) * ENC_STRIDE + ko;
                u32 bh0 = *(const u32*)(ar + 2 * tig);
                u32 bh1 = *(const u32*)(ar + 2 * tig + 8);
                u32 bl0 = *(const u32*)(arl + 2 * tig);
                u32 bl1 = *(const u32*)(arl + 2 * tig + 8);
#pragma unroll
                for (int mt = 0; mt < 2; mt++) {
                    MMA16816(acc[mt][nt], ah[mt], bh0, bh1);
                    MMA16816(acc[mt][nt], ah[mt], bl0, bl1);
                    MMA16816(acc[mt][nt], al[mt], bh0, bh1);
                }
            }
        }
    }
    if (tid < 64) {
        float s = 0.f;
#pragma unroll 8
        for (int i = 0; i < 64; i++) s += sq[tid * 64 + i];
        fP[row0 + tid] = (s > 1e-12f) ? 1 : 0;
    }
#pragma unroll
    for (int mt = 0; mt < 2; mt++) {
        int m0 = w * 32 + mt * 16 + g;
        float b0 = bb[m0], b8 = bb[m0 + 8];
#pragma unroll
        for (int nt = 0; nt < 8; nt++) {
            size_t r0 = row0 + nt * 8 + 2 * tig;
            float v;
            v = acc[mt][nt][0] + b0; eP[r0 * 256 + m0]           = packsplit(v > 0.f ? v : 0.f);
            v = acc[mt][nt][1] + b0; eP[(r0 + 1) * 256 + m0]     = packsplit(v > 0.f ? v : 0.f);
            v = acc[mt][nt][2] + b8; eP[r0 * 256 + m0 + 8]       = packsplit(v > 0.f ? v : 0.f);
            v = acc[mt][nt][3] + b8; eP[(r0 + 1) * 256 + m0 + 8] = packsplit(v > 0.f ? v : 0.f);
        }
    }
}

// --------------------------- tail kernel (HMMA) -----------------------------
// 64 rows/CTA (sorted), 512 threads (16 warps), 1 CTA/SM.
// Warp w owns 16 exclusive cols (m = w*16+g) across ALL 8 row-tiles:
// weights fetched once per CTA per column. GEMM1 lerp epilogue -> xs;
// GEMM2 branch W5c -> h1 (overlay e0); GEMM3 Wc2 (warps 0..4) -> out.
#define SR 264
#define PLANE (64 * SR)
#define T_E0H 0
#define T_E0L (1 * PLANE)
#define T_E1H (2 * PLANE)
#define T_E1L (3 * PLANE)
#define T_XSH (4 * PLANE)
#define T_XSL (5 * PLANE)
#define T_FLT (6 * PLANE)
#define TAIL_SMEM (6 * PLANE * 2 + 2048)

__global__ void __launch_bounds__(512, 1)
tail_mma(const float* __restrict__ bc1, const float* __restrict__ bc2,
         float* __restrict__ out) {
    extern __shared__ u16 sh[];
    u16* E0H = sh + T_E0H; u16* E0L = sh + T_E0L;
    u16* E1H = sh + T_E1H; u16* E1L = sh + T_E1L;
    u16* XSH = sh + T_XSH; u16* XSL = sh + T_XSL;
    float* sattn = (float*)(sh + T_FLT);        // [64][4]
    int* sflag = (int*)(sattn + 256);
    int* sperm = sflag + 64;
    int* ssbr  = sperm + 64;
    int* snb   = ssbr + 64;
    float* scratch = (float*)(sh + T_XSH);      // overlays xs (dead till GEMM1 epi)

    const int tid = threadIdx.x, lane = tid & 31, w = tid >> 5;
    const int g = lane >> 2, tig = lane & 3;
    const size_t row0 = (size_t)blockIdx.x * 64;

    // P0: flags (from enc) + sort (64 rows)
    if (tid < 64) {
        int fi = g_fi[row0 + tid], ft = g_ft[row0 + tid];
        sflag[tid] = (fi && ft) ? 1 : (fi ? 2 : (ft ? 3 : 0));
    }
    __syncthreads();
    if (tid == 0) {
        int cnt[4] = {0, 0, 0, 0};
        for (int r = 0; r < 64; r++) cnt[sflag[r]]++;
        int base[4];
        base[1] = 0; base[2] = cnt[1]; base[3] = cnt[1] + cnt[2]; base[0] = base[3] + cnt[3];
        for (int r = 0; r < 64; r++) {
            int f = sflag[r], s = base[f]++;
            sperm[s] = r; ssbr[s] = f;
        }
        *snb = cnt[1];
    }
    __syncthreads();

    // P1: unpack packed split planes (sorted) + per-head dot partials
    {
        int s = tid >> 3, p = tid & 7;
        size_t gr = row0 + sperm[s];
        int k0 = p * 32;
        float d[2][4] = {};
#pragma unroll
        for (int m2 = 0; m2 < 2; m2++) {
            const u32* src = (m2 ? g_ep1 : g_ep0) + gr * 256 + k0;
            u16* PH = m2 ? E1H : E0H;
            u16* PL = m2 ? E1L : E0L;
#pragma unroll
            for (int q = 0; q < 8; q++) {
                uint4 v = *(const uint4*)(src + q * 4);
                int k = k0 + q * 4;
                *(u32*)(PH + s * SR + k)     = (v.x & 0xffffu) | ((v.y & 0xffffu) << 16);
                *(u32*)(PH + s * SR + k + 2) = (v.z & 0xffffu) | ((v.w & 0xffffu) << 16);
                *(u32*)(PL + s * SR + k)     = (v.x >> 16) | (v.y & 0xffff0000u);
                *(u32*)(PL + s * SR + k + 2) = (v.z >> 16) | (v.w & 0xffff0000u);
                float e0 = __uint_as_float(v.x << 16) + __uint_as_float(v.x & 0xffff0000u);
                float e1 = __uint_as_float(v.y << 16) + __uint_as_float(v.y & 0xffff0000u);
                float e2 = __uint_as_float(v.z << 16) + __uint_as_float(v.z & 0xffff0000u);
                float e3 = __uint_as_float(v.w << 16) + __uint_as_float(v.w & 0xffff0000u);
#pragma unroll
                for (int h = 0; h < 4; h++) {
                    const float* wk = g_wk + h * 256 + k;
                    d[m2][h] = fmaf(e0, wk[0], d[m2][h]);
                    d[m2][h] = fmaf(e1, wk[1], d[m2][h]);
                    d[m2][h] = fmaf(e2, wk[2], d[m2][h]);
                    d[m2][h] = fmaf(e3, wk[3], d[m2][h]);
                }
            }
        }
#pragma unroll
        for (int h = 0; h < 4; h++) {
            scratch[(s * 8 + p) * 4 + h] = d[0][h];
            scratch[2048 + (s * 8 + p) * 4 + h] = d[1][h];
        }
    }
    __syncthreads();
    if (tid < 256) {
        int s = tid >> 2, h = tid & 3;
        float d0 = 0.f, d1 = 0.f;
#pragma unroll
        for (int p = 0; p < 8; p++) {
            d0 += scratch[(s * 8 + p) * 4 + h];
            d1 += scratch[2048 + (s * 8 + p) * 4 + h];
        }
        float s0 = (d0 + g_ck[h]) * 0.125f, s1 = (d1 + g_ck[h]) * 0.125f;
        float m = fmaxf(s0, s1);
        float e0 = expf(s0 - m), e1 = expf(s1 - m);
        sattn[s * 4 + h] = e0 / (e0 + e1);
    }
    __syncthreads();
    const int nb = *snb;

    // GEMM1: q0=e0@Wv, q1=e1@Wv over all 8 tiles (16 cols/warp); lerp -> xs
    if (nb > 0) {
        const int m = w * 16 + g;
        const int h = w >> 2;   // head = col/64
        float q0a[8][4] = {}, q1a[8][4] = {};
#pragma unroll 2
        for (int ks = 0; ks < 16; ks++) {
            size_t o = (size_t)m * 256 + ks * 16 + 2 * tig, o8 = o + 2048;
            u32 ah[4] = {*(const u32*)(g_Wvh + o), *(const u32*)(g_Wvh + o8),
                         *(const u32*)(g_Wvh + o + 8), *(const u32*)(g_Wvh + o8 + 8)};
            u32 al[4] = {*(const u32*)(g_Wvl + o), *(const u32*)(g_Wvl + o8),
                         *(const u32*)(g_Wvl + o + 8), *(const u32*)(g_Wvl + o8 + 8)};
#pragma unroll
            for (int nt = 0; nt < 8; nt++) {
                if (nt * 8 < nb) {
                    int base = (nt * 8 + g) * SR + ks * 16 + 2 * tig;
                    u32 x0h0 = *(const u32*)(E0H + base), x0h1 = *(const u32*)(E0H + base + 8);
                    u32 x0l0 = *(const u32*)(E0L + base), x0l1 = *(const u32*)(E0L + base + 8);
                    u32 x1h0 = *(const u32*)(E1H + base), x1h1 = *(const u32*)(E1H + base + 8);
                    u32 x1l0 = *(const u32*)(E1L + base), x1l1 = *(const u32*)(E1L + base + 8);
                    MMA16816(q0a[nt], ah, x0h0, x0h1);
                    MMA16816(q0a[nt], ah, x0l0, x0l1);
                    MMA16816(q0a[nt], al, x0h0, x0h1);
                    MMA16816(q1a[nt], ah, x1h0, x1h1);
                    MMA16816(q1a[nt], ah, x1l0, x1l1);
                    MMA16816(q1a[nt], al, x1h0, x1h1);
                }
            }
        }
#pragma unroll
        for (int nt = 0; nt < 8; nt++) {
            if (nt * 8 < nb) {
                int r0 = nt * 8 + 2 * tig;
#pragma unroll
                for (int pr = 0; pr < 2; pr++) {
                    int r = r0 + pr;
                    if (r < nb) {
                        float a0 = sattn[r * 4 + h];
                        float v0 = fmaf(a0, q0a[nt][pr] - q1a[nt][pr], q1a[nt][pr]);
                        float v8 = fmaf(a0, q0a[nt][2 + pr] - q1a[nt][2 + pr],
                                        q1a[nt][2 + pr]);
                        u16 hh, ll;
                        splitf(v0, hh, ll); XSH[r * SR + m] = hh;     XSL[r * SR + m] = ll;
                        splitf(v8, hh, ll); XSH[r * SR + m + 8] = hh; XSL[r * SR + m + 8] = ll;
                    }
                }
            }
        }
    }
    __syncthreads();

    // P4: xs for non-both rows (copy e0/e1 or zero); 512 tasks, one pass
    {
        int s = tid >> 3, q = tid & 7;
        if (s >= nb) {
            int f = ssbr[s];
            uint4 z = make_uint4(0, 0, 0, 0);
            uint4 vh = z, vl = z;
            if (f == 2) {
                vh = ((const uint4*)(E0H + s * SR))[q];
                vl = ((const uint4*)(E0L + s * SR))[q];
            } else if (f == 3) {
                vh = ((const uint4*)(E1H + s * SR))[q];
                vl = ((const uint4*)(E1L + s * SR))[q];
            }
            ((uint4*)(XSH + s * SR))[q] = vh;
            ((uint4*)(XSL + s * SR))[q] = vl;
            // each q covers 8 u16; need 256 u16 per row -> 32 uint4; q covers 4
#pragma unroll
            for (int j = 1; j < 4; j++) {
                uint4 wh = z, wl = z;
                if (f == 2) {
                    wh = ((const uint4*)(E0H + s * SR))[q + 8 * j];
                    wl = ((const uint4*)(E0L + s * SR))[q + 8 * j];
                } else if (f == 3) {
                    wh = ((const uint4*)(E1H + s * SR))[q + 8 * j];
                    wl = ((const uint4*)(E1L + s * SR))[q + 8 * j];
                }
                ((uint4*)(XSH + s * SR))[q + 8 * j] = wh;
                ((uint4*)(XSL + s * SR))[q + 8 * j] = wl;
            }
        }
    }
    __syncthreads();

    // GEMM2: h1 = relu(xs @ W5c[branch] + bias) -> overlay e0 planes
    {
        const int m = w * 16 + g;
        float a2[8][4] = {};
        for (int seg = 1; seg <= 3; seg++) {
            u32 ntm = 0;
            for (int i = 0; i < 64; i++)
                if (ssbr[i] == seg) ntm |= 1u << (i >> 3);
            if (!ntm) continue;
            const u16* WH = g_W5h + (size_t)(seg - 1) * 65536;
            const u16* WL = g_W5l + (size_t)(seg - 1) * 65536;
#pragma unroll 2
            for (int ks = 0; ks < 16; ks++) {
                size_t o = (size_t)m * 256 + ks * 16 + 2 * tig, o8 = o + 2048;
                u32 ah[4] = {*(const u32*)(WH + o), *(const u32*)(WH + o8),
                             *(const u32*)(WH + o + 8), *(const u32*)(WH + o8 + 8)};
                u32 al[4] = {*(const u32*)(WL + o), *(const u32*)(WL + o8),
                             *(const u32*)(WL + o + 8), *(const u32*)(WL + o8 + 8)};
#pragma unroll
                for (int nt = 0; nt < 8; nt++) {
                    if (!((ntm >> nt) & 1)) continue;
                    int s = nt * 8 + g;
                    bool on = (ssbr[s] == seg);
                    int base = s * SR + ks * 16 + 2 * tig;
                    u32 bh0 = 0, bh1 = 0, bl0 = 0, bl1 = 0;
                    if (on) {
                        bh0 = *(const u32*)(XSH + base); bh1 = *(const u32*)(XSH + base + 8);
                        bl0 = *(const u32*)(XSL + base); bl1 = *(const u32*)(XSL + base + 8);
                    }
                    MMA16816(a2[nt], ah, bh0, bh1);
                    MMA16816(a2[nt], ah, bl0, bl1);
                    MMA16816(a2[nt], al, bh0, bh1);
                }
            }
        }
        __syncthreads();  // all xs/e reads done before h1 overlay of E0
#pragma unroll
        for (int nt = 0; nt < 8; nt++) {
            int r0 = nt * 8 + 2 * tig;
#pragma unroll
            for (int pr = 0; pr < 2; pr++) {
                int r = r0 + pr;
                int f = ssbr[r];
                float b0 = f ? g_b5c[(f - 1) * 256 + m] : bc1[m];
                float b8 = f ? g_b5c[(f - 1) * 256 + m + 8] : bc1[m + 8];
                float v0 = a2[nt][pr] + b0;     v0 = v0 > 0.f ? v0 : 0.f;
                float v8 = a2[nt][2 + pr] + b8; v8 = v8 > 0.f ? v8 : 0.f;
                u16 hh, ll;
                splitf(v0, hh, ll); E0H[r * SR + m] = hh;     E0L[r * SR + m] = ll;
                splitf(v8, hh, ll); E0H[r * SR + m + 8] = hh; E0L[r * SR + m + 8] = ll;
            }
        }
    }
    __syncthreads();

    // GEMM3: out = h1 @ Wc2 + bc2 (warps 0..4, 16 cols each, all 8 tiles)
    if (w < 5) {
        const int m = w * 16 + g;
        float a3[8][4] = {};
#pragma unroll 2
        for (int ks = 0; ks < 16; ks++) {
            size_t o = (size_t)m * 256 + ks * 16 + 2 * tig, o8 = o + 2048;
            u32 ah[4] = {*(const u32*)(g_Wch + o), *(const u32*)(g_Wch + o8),
                         *(const u32*)(g_Wch + o + 8), *(const u32*)(g_Wch + o8 + 8)};
            u32 al[4] = {*(const u32*)(g_Wcl + o), *(const u32*)(g_Wcl + o8),
                         *(const u32*)(g_Wcl + o + 8), *(const u32*)(g_Wcl + o8 + 8)};
#pragma unroll
            for (int nt = 0; nt < 8; nt++) {
                int base = (nt * 8 + g) * SR + ks * 16 + 2 * tig;
                u32 bh0 = *(const u32*)(E0H + base), bh1 = *(const u32*)(E0H + base + 8);
                u32 bl0 = *(const u32*)(E0L + base), bl1 = *(const u32*)(E0L + base + 8);
                MMA16816(a3[nt], ah, bh0, bh1);
                MMA16816(a3[nt], ah, bl0, bl1);
                MMA16816(a3[nt], al, bh0, bh1);
            }
        }
#pragma unroll
        for (int nt = 0; nt < 8; nt++) {
            int r0 = nt * 8 + 2 * tig;
#pragma unroll
            for (int pr = 0; pr < 2; pr++) {
                size_t ro = (row0 + sperm[r0 + pr]) * 80;
                out[ro + m]     = a3[nt][pr] + bc2[m];
                out[ro + m + 8] = a3[nt][2 + pr] + bc2[m + 8];
            }
        }
    }
}

// ------------------------------- launch ------------------------------------
extern "C" void kernel_launch(void* const* d_in, const int* in_sizes, int n_in,
                              void* d_out, int out_size) {
    const float* img  = (const float*)d_in[0];
    const float* txt  = (const float*)d_in[1];
    const float* W_ie = (const float*)d_in[2];
    const float* b_ie = (const float*)d_in[3];
    const float* W_te = (const float*)d_in[4];
    const float* b_te = (const float*)d_in[5];
    const float* fq   = (const float*)d_in[6];
    const float* Wq   = (const float*)d_in[7];
    const float* bq   = (const float*)d_in[8];
    const float* Wk   = (const float*)d_in[9];
    const float* bk   = (const float*)d_in[10];
    const float* Wv   = (const float*)d_in[11];
    const float* bv   = (const float*)d_in[12];
    const float* Wo   = (const float*)d_in[13];
    const float* bo   = (const float*)d_in[14];
    const float* W_ip = (const float*)d_in[15];
    const float* b_ip = (const float*)d_in[16];
    const float* W_tp = (const float*)d_in[17];
    const float* b_tp = (const float*)d_in[18];
    const float* W_fp = (const float*)d_in[19];
    const float* b_fp = (const float*)d_in[20];
    const float* Wc1  = (const float*)d_in[21];
    const float* bc1  = (const float*)d_in[22];
    const float* Wc2  = (const float*)d_in[23];
    const float* bc2  = (const float*)d_in[24];
    float* out = (float*)d_out;

    const int B = in_sizes[0] / 512;

    setup_all<<<33, 256>>>(fq, Wq, bq, Wk, bk, bv, Wo, bo, W_fp, b_fp);
    setup_fuse<<<49, 256>>>(W_ip, W_tp, Wc1, b_ip, b_tp, bc1);
    setup_conv<<<1024, 256>>>(W_ie, W_te);
    setup_conv2<<<1104, 256>>>(Wv, Wc2);

    cudaFuncSetAttribute(enc_kernel, cudaFuncAttributeMaxDynamicSharedMemorySize,
                         ENC_SMEM);
    enc_kernel<<<dim3(B / 64, 2), 256, ENC_SMEM>>>(img, txt, b_ie, b_te);

    cudaFuncSetAttribute(tail_mma, cudaFuncAttributeMaxDynamicSharedMemorySize,
                         TAIL_SMEM);
    tail_mma<<<B / 64, 512, TAIL_SMEM>>>(bc1, bc2, out);
}